// round 6
// baseline (speedup 1.0000x reference)
#include <cuda_runtime.h>
#include <cuda_bf16.h>
#include <cstdint>

#define NHEAD 16
#define DK 64
#define SEQ 2048
#define BATCH 2
#define DMODEL 1024
#define BS (BATCH*SEQ)

static const size_t OUT_ELEMS = (size_t)BATCH * SEQ * DMODEL;   // 4,194,304

// -------- scratch (static device globals; no runtime allocation) --------
__device__ __nv_bfloat16 g_xhi[(size_t)BS * DMODEL];
__device__ __nv_bfloat16 g_xlo[(size_t)BS * DMODEL];
__device__ __nv_bfloat16 g_wqt_hi[(size_t)DMODEL * DMODEL];
__device__ __nv_bfloat16 g_wqt_lo[(size_t)DMODEL * DMODEL];
__device__ __nv_bfloat16 g_wkt_hi[(size_t)DMODEL * DMODEL];
__device__ __nv_bfloat16 g_wkt_lo[(size_t)DMODEL * DMODEL];
__device__ __nv_bfloat16 g_wft_hi[(size_t)DMODEL * DMODEL];
__device__ __nv_bfloat16 g_wft_lo[(size_t)DMODEL * DMODEL];
__device__ __nv_bfloat16 g_wvt  [(size_t)DMODEL * DMODEL];
__device__ __nv_bfloat16 g_qhi[(size_t)BATCH * NHEAD * SEQ * DK];
__device__ __nv_bfloat16 g_qlo[(size_t)BATCH * NHEAD * SEQ * DK];
__device__ __nv_bfloat16 g_khi[(size_t)BATCH * NHEAD * SEQ * DK];
__device__ __nv_bfloat16 g_klo[(size_t)BATCH * NHEAD * SEQ * DK];
__device__ __nv_bfloat16 g_vp [(size_t)BATCH * NHEAD * SEQ * DK];
__device__ __nv_bfloat16 g_ohi[(size_t)BS * DMODEL];
__device__ __nv_bfloat16 g_olo[(size_t)BS * DMODEL];
__device__ float         g_rinv[(size_t)BATCH * NHEAD * SEQ];

// ======================= helpers =======================
__device__ __forceinline__ uint32_t smem_u32(const void* p) {
    uint32_t a;
    asm("{ .reg .u64 t; cvta.to.shared.u64 t, %1; cvt.u32.u64 %0, t; }" : "=r"(a) : "l"(p));
    return a;
}
__device__ __forceinline__ void ldsm4(uint32_t* r, uint32_t addr) {
    asm volatile("ldmatrix.sync.aligned.m8n8.x4.shared.b16 {%0,%1,%2,%3}, [%4];"
                 : "=r"(r[0]), "=r"(r[1]), "=r"(r[2]), "=r"(r[3]) : "r"(addr));
}
__device__ __forceinline__ void ldsm2(uint32_t* r, uint32_t addr) {
    asm volatile("ldmatrix.sync.aligned.m8n8.x2.shared.b16 {%0,%1}, [%2];"
                 : "=r"(r[0]), "=r"(r[1]) : "r"(addr));
}
__device__ __forceinline__ void ldsm2t(uint32_t* r, uint32_t addr) {
    asm volatile("ldmatrix.sync.aligned.m8n8.x2.trans.shared.b16 {%0,%1}, [%2];"
                 : "=r"(r[0]), "=r"(r[1]) : "r"(addr));
}
__device__ __forceinline__ void mma_bf(float* c, const uint32_t* a, const uint32_t* b) {
    asm volatile(
        "mma.sync.aligned.m16n8k16.row.col.f32.bf16.bf16.f32 "
        "{%0,%1,%2,%3}, {%4,%5,%6,%7}, {%8,%9}, {%0,%1,%2,%3};"
        : "+f"(c[0]), "+f"(c[1]), "+f"(c[2]), "+f"(c[3])
        : "r"(a[0]), "r"(a[1]), "r"(a[2]), "r"(a[3]), "r"(b[0]), "r"(b[1]));
}
__device__ __forceinline__ void cp16(uint32_t saddr, const void* g) {
    asm volatile("cp.async.cg.shared.global [%0], [%1], 16;" :: "r"(saddr), "l"(g));
}
#define CP_COMMIT asm volatile("cp.async.commit_group;")
#define CP_WAIT0  asm volatile("cp.async.wait_group 0;")
#define CP_WAIT1  asm volatile("cp.async.wait_group 1;")

__device__ __forceinline__ uint32_t pack_bf2f(float a, float b) {
    __nv_bfloat162 h = __floats2bfloat162_rn(a, b);
    return *reinterpret_cast<uint32_t*>(&h);
}
__device__ __forceinline__ void split2(float v0, float v1, uint32_t& hi, uint32_t& lo) {
    __nv_bfloat16 h0 = __float2bfloat16(v0), h1 = __float2bfloat16(v1);
    __nv_bfloat16 l0 = __float2bfloat16(v0 - __bfloat162float(h0));
    __nv_bfloat16 l1 = __float2bfloat16(v1 - __bfloat162float(h1));
    __nv_bfloat162 hh; hh.x = h0; hh.y = h1;
    __nv_bfloat162 ll; ll.x = l0; ll.y = l1;
    hi = *reinterpret_cast<uint32_t*>(&hh);
    lo = *reinterpret_cast<uint32_t*>(&ll);
}
__device__ __forceinline__ float warp_sum(float v) {
    #pragma unroll
    for (int o = 16; o > 0; o >>= 1) v += __shfl_xor_sync(0xffffffffu, v, o);
    return v;
}

// ============================================================================
// prep 1: split qkv into bf16 hi/lo planes
// ============================================================================
__global__ __launch_bounds__(256)
void split_x(const float* __restrict__ x)
{
    size_t i = ((size_t)blockIdx.x * 256 + threadIdx.x) * 4;
    float4 v = *(const float4*)(x + i);
    uint32_t h0, l0, h1, l1;
    split2(v.x, v.y, h0, l0);
    split2(v.z, v.w, h1, l1);
    *(uint2*)(g_xhi + i) = make_uint2(h0, h1);
    *(uint2*)(g_xlo + i) = make_uint2(l0, l1);
}

// ============================================================================
// prep 2: transpose + split weights -> [n][k] bf16 planes
// ============================================================================
__global__ __launch_bounds__(256)
void wtrans(const float* __restrict__ wq, const float* __restrict__ wk,
            const float* __restrict__ wv, const float* __restrict__ wf)
{
    const int z = blockIdx.z;
    const float* W = (z == 0) ? wq : (z == 1) ? wk : (z == 2) ? wv : wf;
    __nv_bfloat16* Ohi = (z == 0) ? g_wqt_hi : (z == 1) ? g_wkt_hi : (z == 2) ? g_wvt : g_wft_hi;
    __nv_bfloat16* Olo = (z == 0) ? g_wqt_lo : (z == 1) ? g_wkt_lo : (z == 3) ? g_wft_lo : nullptr;

    __shared__ float t[32][33];
    const int n0 = blockIdx.x * 32, k0 = blockIdx.y * 32;
    const int tx = threadIdx.x & 31, ty = threadIdx.x >> 5;
    #pragma unroll
    for (int j = 0; j < 4; j++)
        t[ty + 8 * j][tx] = W[(size_t)(k0 + ty + 8 * j) * DMODEL + n0 + tx];
    __syncthreads();
    #pragma unroll
    for (int j = 0; j < 4; j++) {
        float v = t[tx][ty + 8 * j];
        __nv_bfloat16 h = __float2bfloat16(v);
        size_t off = (size_t)(n0 + ty + 8 * j) * DMODEL + k0 + tx;
        Ohi[off] = h;
        if (Olo) Olo[off] = __float2bfloat16(v - __bfloat162float(h));
    }
}

// ============================================================================
// GEMM Q/K projection (bf16x3), 2-stage cp.async pipeline.
// Stage layout (bytes): Ah 10240 | Al 10240 | Bh 5120 | Bl 5120 = 30720.
// ============================================================================
static constexpr int QK_STG = 30720;
static constexpr int QK_SMEM = 2 * QK_STG;

__global__ __launch_bounds__(256)
void gemm_qk()
{
    extern __shared__ char dsm[];
    const uint32_t uS = smem_u32(dsm);
    const int z = blockIdx.z;
    const __nv_bfloat16* Whi = z ? g_wkt_hi : g_wqt_hi;
    const __nv_bfloat16* Wlo = z ? g_wkt_lo : g_wqt_lo;
    const int h  = blockIdx.x;
    const int n0 = h * 64;
    const int m0 = blockIdx.y * 128;

    const int tid = threadIdx.x;
    const int w = tid >> 5, lane = tid & 31;
    const int wm = w >> 1, wn = w & 1;

    float c[2][4][4];
    #pragma unroll
    for (int mi = 0; mi < 2; mi++)
        #pragma unroll
        for (int ni = 0; ni < 4; ni++)
            #pragma unroll
            for (int r = 0; r < 4; r++) c[mi][ni][r] = 0.0f;

    // prefetch macro body
    #define QK_PREFETCH(KC, ST) do {                                            \
        const int _k0 = (KC) * 32;                                              \
        const uint32_t _sb = uS + (ST) * QK_STG;                                \
        _Pragma("unroll")                                                       \
        for (int t = 0; t < 2; t++) {                                           \
            int idx = tid + t * 256; int r = idx >> 2; int c8 = (idx & 3) * 8;  \
            cp16(_sb + (r * 40 + c8) * 2,                                       \
                 g_xhi + (size_t)(m0 + r) * DMODEL + _k0 + c8);                 \
            cp16(_sb + 10240 + (r * 40 + c8) * 2,                               \
                 g_xlo + (size_t)(m0 + r) * DMODEL + _k0 + c8);                 \
        }                                                                       \
        { int r = tid >> 2; int c8 = (tid & 3) * 8;                             \
          cp16(_sb + 20480 + (r * 40 + c8) * 2,                                 \
               Whi + (size_t)(n0 + r) * DMODEL + _k0 + c8);                     \
          cp16(_sb + 25600 + (r * 40 + c8) * 2,                                 \
               Wlo + (size_t)(n0 + r) * DMODEL + _k0 + c8); }                   \
        CP_COMMIT;                                                              \
    } while (0)

    QK_PREFETCH(0, 0);
    for (int kc = 0; kc < 32; kc++) {
        const int cur = kc & 1;
        if (kc < 31) { QK_PREFETCH(kc + 1, cur ^ 1); CP_WAIT1; } else { CP_WAIT0; }
        __syncthreads();
        const uint32_t uAh = uS + cur * QK_STG;
        const uint32_t uAl = uAh + 10240, uBh = uAh + 20480, uBl = uAh + 25600;
        #pragma unroll
        for (int ks = 0; ks < 2; ks++) {
            uint32_t ah[2][4], al[2][4], bh[4][2], bl[4][2];
            #pragma unroll
            for (int mi = 0; mi < 2; mi++) {
                uint32_t off = ((wm * 32 + mi * 16 + (lane & 15)) * 40 + (lane >> 4) * 8 + ks * 16) * 2;
                ldsm4(ah[mi], uAh + off);
                ldsm4(al[mi], uAl + off);
            }
            #pragma unroll
            for (int ni = 0; ni < 4; ni++) {
                uint32_t off = ((wn * 32 + ni * 8 + (lane & 7)) * 40 + ((lane >> 3) & 1) * 8 + ks * 16) * 2;
                ldsm2(bh[ni], uBh + off);
                ldsm2(bl[ni], uBl + off);
            }
            #pragma unroll
            for (int mi = 0; mi < 2; mi++)
                #pragma unroll
                for (int ni = 0; ni < 4; ni++) {
                    mma_bf(c[mi][ni], ah[mi], bh[ni]);
                    mma_bf(c[mi][ni], ah[mi], bl[ni]);
                    mma_bf(c[mi][ni], al[mi], bh[ni]);
                }
        }
        __syncthreads();
    }
    #undef QK_PREFETCH

    const float scale = z ? 1.0f : 0.125f;
    __nv_bfloat16* hiDst = z ? g_khi : g_qhi;
    __nv_bfloat16* loDst = z ? g_klo : g_qlo;
    #pragma unroll
    for (int mi = 0; mi < 2; mi++)
        #pragma unroll
        for (int ni = 0; ni < 4; ni++) {
            int col = wn * 32 + ni * 8 + (lane & 3) * 2;
            #pragma unroll
            for (int half = 0; half < 2; half++) {
                int row = m0 + wm * 32 + mi * 16 + (lane >> 2) + half * 8;
                int b = row >> 11, s = row & 2047;
                size_t off = ((size_t)((b * NHEAD + h) * SEQ + s)) * DK + col;
                uint32_t hi, lo;
                split2(c[mi][ni][half * 2] * scale, c[mi][ni][half * 2 + 1] * scale, hi, lo);
                *(uint32_t*)(hiDst + off) = hi;
                *(uint32_t*)(loDst + off) = lo;
            }
        }
}

// ============================================================================
// GEMM V projection (plain bf16), 2-stage cp.async.
// Stage: Ah 10240 | Bh 5120 = 15360.
// ============================================================================
static constexpr int V_STG = 15360;
static constexpr int V_SMEM = 2 * V_STG;

__global__ __launch_bounds__(256)
void gemm_v()
{
    extern __shared__ char dsm[];
    const uint32_t uS = smem_u32(dsm);
    const int h  = blockIdx.x;
    const int n0 = h * 64;
    const int m0 = blockIdx.y * 128;

    const int tid = threadIdx.x;
    const int w = tid >> 5, lane = tid & 31;
    const int wm = w >> 1, wn = w & 1;

    float c[2][4][4];
    #pragma unroll
    for (int mi = 0; mi < 2; mi++)
        #pragma unroll
        for (int ni = 0; ni < 4; ni++)
            #pragma unroll
            for (int r = 0; r < 4; r++) c[mi][ni][r] = 0.0f;

    #define V_PREFETCH(KC, ST) do {                                             \
        const int _k0 = (KC) * 32;                                              \
        const uint32_t _sb = uS + (ST) * V_STG;                                 \
        _Pragma("unroll")                                                       \
        for (int t = 0; t < 2; t++) {                                           \
            int idx = tid + t * 256; int r = idx >> 2; int c8 = (idx & 3) * 8;  \
            cp16(_sb + (r * 40 + c8) * 2,                                       \
                 g_xhi + (size_t)(m0 + r) * DMODEL + _k0 + c8);                 \
        }                                                                       \
        { int r = tid >> 2; int c8 = (tid & 3) * 8;                             \
          cp16(_sb + 10240 + (r * 40 + c8) * 2,                                 \
               g_wvt + (size_t)(n0 + r) * DMODEL + _k0 + c8); }                 \
        CP_COMMIT;                                                              \
    } while (0)

    V_PREFETCH(0, 0);
    for (int kc = 0; kc < 32; kc++) {
        const int cur = kc & 1;
        if (kc < 31) { V_PREFETCH(kc + 1, cur ^ 1); CP_WAIT1; } else { CP_WAIT0; }
        __syncthreads();
        const uint32_t uAh = uS + cur * V_STG;
        const uint32_t uBh = uAh + 10240;
        #pragma unroll
        for (int ks = 0; ks < 2; ks++) {
            uint32_t ah[2][4], bh[4][2];
            #pragma unroll
            for (int mi = 0; mi < 2; mi++)
                ldsm4(ah[mi], uAh + ((wm * 32 + mi * 16 + (lane & 15)) * 40 + (lane >> 4) * 8 + ks * 16) * 2);
            #pragma unroll
            for (int ni = 0; ni < 4; ni++)
                ldsm2(bh[ni], uBh + ((wn * 32 + ni * 8 + (lane & 7)) * 40 + ((lane >> 3) & 1) * 8 + ks * 16) * 2);
            #pragma unroll
            for (int mi = 0; mi < 2; mi++)
                #pragma unroll
                for (int ni = 0; ni < 4; ni++)
                    mma_bf(c[mi][ni], ah[mi], bh[ni]);
        }
        __syncthreads();
    }
    #undef V_PREFETCH

    #pragma unroll
    for (int mi = 0; mi < 2; mi++)
        #pragma unroll
        for (int ni = 0; ni < 4; ni++) {
            int col = wn * 32 + ni * 8 + (lane & 3) * 2;
            #pragma unroll
            for (int half = 0; half < 2; half++) {
                int row = m0 + wm * 32 + mi * 16 + (lane >> 2) + half * 8;
                int b = row >> 11, s = row & 2047;
                size_t off = ((size_t)((b * NHEAD + h) * SEQ + s)) * DK + col;
                *(uint32_t*)(g_vp + off) =
                    pack_bf2f(c[mi][ni][half * 2], c[mi][ni][half * 2 + 1]);
            }
        }
}

// ============================================================================
// Fused attention: scores (bf16x3) -> exp (unnormalized, masked) -> attn write
// -> PV (bf16, unnormalized) -> O normalize -> g_ohi/g_olo, g_rinv.
// CTA: 128 q-rows x full 2048 k, k-tiles of 64.  8 warps = 4(wm) x 2(wn).
// SMEM (dynamic): Qh 18432 | Ql 18432 | stage{Kh 9216|Kl 9216|V 9216} x2 = 92160 B.
// ============================================================================
static constexpr int AF_QH = 0;
static constexpr int AF_QL = 18432;
static constexpr int AF_STG0 = 36864;
static constexpr int AF_STG  = 27648;
static constexpr int AF_SMEM = AF_STG0 + 2 * AF_STG;   // 92160

__global__ __launch_bounds__(256)
void attn_fused(const int* __restrict__ mask, float* __restrict__ attn)
{
    extern __shared__ char dsm[];
    const uint32_t uS = smem_u32(dsm);
    __shared__ float rsum2[128][2];
    __shared__ float inv_s[128];

    const int tid = threadIdx.x;
    const int w = tid >> 5, lane = tid & 31;
    const int wm = w >> 1, wn = w & 1;
    const int q0 = blockIdx.x * 128;
    const int bh = blockIdx.y;
    const int b  = bh >> 4, h = bh & 15;

    const size_t plane = (size_t)bh * SEQ * DK;

    // load Q tiles (hi/lo) into smem, stride 72
    #pragma unroll
    for (int t = 0; t < 4; t++) {
        int idx = tid + t * 256;
        int r = idx >> 3, c8 = (idx & 7) * 8;
        *(uint4*)(dsm + AF_QH + (r * 72 + c8) * 2) =
            *(const uint4*)(g_qhi + plane + (size_t)(q0 + r) * DK + c8);
        *(uint4*)(dsm + AF_QL + (r * 72 + c8) * 2) =
            *(const uint4*)(g_qlo + plane + (size_t)(q0 + r) * DK + c8);
    }

    #define AF_PREFETCH(TI, ST) do {                                            \
        const int _k0 = (TI) * 64;                                              \
        const uint32_t _sb = uS + AF_STG0 + (ST) * AF_STG;                      \
        _Pragma("unroll")                                                       \
        for (int t = 0; t < 2; t++) {                                           \
            int idx = tid + t * 256; int r = idx >> 3; int c8 = (idx & 7) * 8;  \
            cp16(_sb + (r * 72 + c8) * 2,                                       \
                 g_khi + plane + (size_t)(_k0 + r) * DK + c8);                  \
            cp16(_sb + 9216 + (r * 72 + c8) * 2,                                \
                 g_klo + plane + (size_t)(_k0 + r) * DK + c8);                  \
            cp16(_sb + 18432 + (r * 72 + c8) * 2,                               \
                 g_vp + plane + (size_t)(_k0 + r) * DK + c8);                   \
        }                                                                       \
        CP_COMMIT;                                                              \
    } while (0)

    AF_PREFETCH(0, 0);

    const uint32_t uQh = uS + AF_QH, uQl = uS + AF_QL;
    float c_o[2][8][4];
    #pragma unroll
    for (int mi = 0; mi < 2; mi++)
        #pragma unroll
        for (int nd = 0; nd < 8; nd++)
            #pragma unroll
            for (int r = 0; r < 4; r++) c_o[mi][nd][r] = 0.0f;
    float rs[2][2] = {{0.0f, 0.0f}, {0.0f, 0.0f}};

    float* aplane = attn + (size_t)bh * SEQ * SEQ;
    const int* mplane = mask + (size_t)b * SEQ * SEQ;

    for (int ti = 0; ti < SEQ / 64; ti++) {
        const int cur = ti & 1;
        if (ti < SEQ / 64 - 1) { AF_PREFETCH(ti + 1, cur ^ 1); CP_WAIT1; } else { CP_WAIT0; }
        __syncthreads();
        const uint32_t uKh = uS + AF_STG0 + cur * AF_STG;
        const uint32_t uKl = uKh + 9216;
        const uint32_t uV  = uKh + 18432;

        // ---- scores: c = Q . K^T over dk=64, bf16x3 ----
        float c[2][4][4];
        #pragma unroll
        for (int mi = 0; mi < 2; mi++)
            #pragma unroll
            for (int ni = 0; ni < 4; ni++)
                #pragma unroll
                for (int r = 0; r < 4; r++) c[mi][ni][r] = 0.0f;

        #pragma unroll
        for (int ks = 0; ks < 4; ks++) {
            uint32_t ah[2][4], al[2][4], bh2[4][2], bl2[4][2];
            #pragma unroll
            for (int mi = 0; mi < 2; mi++) {
                uint32_t off = ((wm * 32 + mi * 16 + (lane & 15)) * 72 + (lane >> 4) * 8 + ks * 16) * 2;
                ldsm4(ah[mi], uQh + off);
                ldsm4(al[mi], uQl + off);
            }
            #pragma unroll
            for (int ni = 0; ni < 4; ni++) {
                uint32_t off = ((wn * 32 + ni * 8 + (lane & 7)) * 72 + ((lane >> 3) & 1) * 8 + ks * 16) * 2;
                ldsm2(bh2[ni], uKh + off);
                ldsm2(bl2[ni], uKl + off);
            }
            #pragma unroll
            for (int mi = 0; mi < 2; mi++)
                #pragma unroll
                for (int ni = 0; ni < 4; ni++) {
                    mma_bf(c[mi][ni], ah[mi], bh2[ni]);
                    mma_bf(c[mi][ni], ah[mi], bl2[ni]);
                    mma_bf(c[mi][ni], al[mi], bh2[ni]);
                }
        }

        // ---- mask + exp (unnormalized) + attn write + rowsum ----
        const int k0 = ti * 64;
        #pragma unroll
        for (int mi = 0; mi < 2; mi++)
            #pragma unroll
            for (int ni = 0; ni < 4; ni++) {
                int kcol = k0 + wn * 32 + ni * 8 + (lane & 3) * 2;
                #pragma unroll
                for (int half = 0; half < 2; half++) {
                    int qrow = q0 + wm * 32 + mi * 16 + (lane >> 2) + half * 8;
                    size_t off = (size_t)qrow * SEQ + kcol;
                    int2 mv = *(const int2*)(mplane + off);
                    float e0 = mv.x ? __expf(fminf(c[mi][ni][half * 2],     80.0f)) : 0.0f;
                    float e1 = mv.y ? __expf(fminf(c[mi][ni][half * 2 + 1], 80.0f)) : 0.0f;
                    c[mi][ni][half * 2]     = e0;
                    c[mi][ni][half * 2 + 1] = e1;
                    rs[mi][half] += e0 + e1;
                    *(float2*)(aplane + off) = make_float2(e0, e1);
                }
            }

        // ---- PV: O += P(bf16, from regs) @ V ----
        #pragma unroll
        for (int kk = 0; kk < 2; kk++) {
            uint32_t a[2][4];
            #pragma unroll
            for (int mi = 0; mi < 2; mi++) {
                a[mi][0] = pack_bf2f(c[mi][kk * 2][0],     c[mi][kk * 2][1]);
                a[mi][1] = pack_bf2f(c[mi][kk * 2][2],     c[mi][kk * 2][3]);
                a[mi][2] = pack_bf2f(c[mi][kk * 2 + 1][0], c[mi][kk * 2 + 1][1]);
                a[mi][3] = pack_bf2f(c[mi][kk * 2 + 1][2], c[mi][kk * 2 + 1][3]);
            }
            #pragma unroll
            for (int nd = 0; nd < 8; nd++) {
                uint32_t b2[2];
                ldsm2t(b2, uV + ((wn * 32 + kk * 16 + (lane & 15)) * 72 + nd * 8) * 2);
                #pragma unroll
                for (int mi = 0; mi < 2; mi++)
                    mma_bf(c_o[mi][nd], a[mi], b2);
            }
        }
        __syncthreads();
    }
    #undef AF_PREFETCH

    // ---- rowsum reduce -> inv ----
    #pragma unroll
    for (int mi = 0; mi < 2; mi++)
        #pragma unroll
        for (int half = 0; half < 2; half++) {
            float v = rs[mi][half];
            v += __shfl_xor_sync(0xffffffffu, v, 1);
            v += __shfl_xor_sync(0xffffffffu, v, 2);
            if ((lane & 3) == 0)
                rsum2[wm * 32 + mi * 16 + (lane >> 2) + half * 8][wn] = v;
        }
    __syncthreads();
    if (tid < 128) {
        float inv = 1.0f / (rsum2[tid][0] + rsum2[tid][1]);
        inv_s[tid] = inv;
        g_rinv[(size_t)bh * SEQ + q0 + tid] = inv;
    }

    // ---- O reduce across wn, scale by inv, split to bf16 hi/lo ----
    float* Osm = (float*)dsm;     // reuse Q area: 128 x 68 floats = 34816 B
    __syncthreads();
    if (wn == 0) {
        #pragma unroll
        for (int mi = 0; mi < 2; mi++)
            #pragma unroll
            for (int nd = 0; nd < 8; nd++) {
                int d = nd * 8 + (lane & 3) * 2;
                #pragma unroll
                for (int half = 0; half < 2; half++) {
                    int row = wm * 32 + mi * 16 + (lane >> 2) + half * 8;
                    Osm[row * 68 + d]     = c_o[mi][nd][half * 2];
                    Osm[row * 68 + d + 1] = c_o[mi][nd][half * 2 + 1];
                }
            }
    }
    __syncthreads();
    if (wn == 1) {
        #pragma unroll
        for (int mi = 0; mi < 2; mi++)
            #pragma unroll
            for (int nd = 0; nd < 8; nd++) {
                int d = nd * 8 + (lane & 3) * 2;
                #pragma unroll
                for (int half = 0; half < 2; half++) {
                    int row = wm * 32 + mi * 16 + (lane >> 2) + half * 8;
                    Osm[row * 68 + d]     += c_o[mi][nd][half * 2];
                    Osm[row * 68 + d + 1] += c_o[mi][nd][half * 2 + 1];
                }
            }
    }
    __syncthreads();

    {
        const int row = tid >> 1;
        const int d0  = (tid & 1) * 32;
        const float inv = inv_s[row];
        const int s = q0 + row;
        size_t off = (size_t)(b * SEQ + s) * DMODEL + h * DK + d0;
        #pragma unroll
        for (int dd = 0; dd < 16; dd++) {
            float v0 = Osm[row * 68 + d0 + dd * 2]     * inv;
            float v1 = Osm[row * 68 + d0 + dd * 2 + 1] * inv;
            uint32_t hi, lo;
            split2(v0, v1, hi, lo);
            *(uint32_t*)(g_ohi + off + dd * 2) = hi;
            *(uint32_t*)(g_olo + off + dd * 2) = lo;
        }
    }
}

// ============================================================================
// normalize attn in place: attn[row, :] *= rinv[row]
// ============================================================================
__global__ __launch_bounds__(256)
void norm_attn(float* __restrict__ attn)
{
    size_t i = ((size_t)blockIdx.x * 256 + threadIdx.x) * 4;
    const float inv = g_rinv[i >> 11];
    float4 v = *(float4*)(attn + i);
    v.x *= inv; v.y *= inv; v.z *= inv; v.w *= inv;
    *(float4*)(attn + i) = v;
}

// ============================================================================
// FC (bf16x3) + residual, 2-stage cp.async.  Same stage layout as gemm_qk.
// ============================================================================
__global__ __launch_bounds__(256)
void gemm_fc(const float* __restrict__ qkv, float* __restrict__ out)
{
    extern __shared__ char dsm[];
    const uint32_t uS = smem_u32(dsm);
    const int n0 = blockIdx.x * 64;
    const int m0 = blockIdx.y * 128;

    const int tid = threadIdx.x;
    const int w = tid >> 5, lane = tid & 31;
    const int wm = w >> 1, wn = w & 1;

    float c[2][4][4];
    #pragma unroll
    for (int mi = 0; mi < 2; mi++)
        #pragma unroll
        for (int ni = 0; ni < 4; ni++)
            #pragma unroll
            for (int r = 0; r < 4; r++) c[mi][ni][r] = 0.0f;

    #define FC_PREFETCH(KC, ST) do {                                            \
        const int _k0 = (KC) * 32;                                              \
        const uint32_t _sb = uS + (ST) * QK_STG;                                \
        _Pragma("unroll")                                                       \
        for (int t = 0; t < 2; t++) {                                           \
            int idx = tid + t * 256; int r = idx >> 2; int c8 = (idx & 3) * 8;  \
            cp16(_sb + (r * 40 + c8) * 2,                                       \
                 g_ohi + (size_t)(m0 + r) * DMODEL + _k0 + c8);                 \
            cp16(_sb + 10240 + (r * 40 + c8) * 2,                               \
                 g_olo + (size_t)(m0 + r) * DMODEL + _k0 + c8);                 \
        }                                                                       \
        { int r = tid >> 2; int c8 = (tid & 3) * 8;                             \
          cp16(_sb + 20480 + (r * 40 + c8) * 2,                                 \
               g_wft_hi + (size_t)(n0 + r) * DMODEL + _k0 + c8);                \
          cp16(_sb + 25600 + (r * 40 + c8) * 2,                                 \
               g_wft_lo + (size_t)(n0 + r) * DMODEL + _k0 + c8); }              \
        CP_COMMIT;                                                              \
    } while (0)

    FC_PREFETCH(0, 0);
    for (int kc = 0; kc < 32; kc++) {
        const int cur = kc & 1;
        if (kc < 31) { FC_PREFETCH(kc + 1, cur ^ 1); CP_WAIT1; } else { CP_WAIT0; }
        __syncthreads();
        const uint32_t uAh = uS + cur * QK_STG;
        const uint32_t uAl = uAh + 10240, uBh = uAh + 20480, uBl = uAh + 25600;
        #pragma unroll
        for (int ks = 0; ks < 2; ks++) {
            uint32_t ah[2][4], al[2][4], bh[4][2], bl[4][2];
            #pragma unroll
            for (int mi = 0; mi < 2; mi++) {
                uint32_t off = ((wm * 32 + mi * 16 + (lane & 15)) * 40 + (lane >> 4) * 8 + ks * 16) * 2;
                ldsm4(ah[mi], uAh + off);
                ldsm4(al[mi], uAl + off);
            }
            #pragma unroll
            for (int ni = 0; ni < 4; ni++) {
                uint32_t off = ((wn * 32 + ni * 8 + (lane & 7)) * 40 + ((lane >> 3) & 1) * 8 + ks * 16) * 2;
                ldsm2(bh[ni], uBh + off);
                ldsm2(bl[ni], uBl + off);
            }
            #pragma unroll
            for (int mi = 0; mi < 2; mi++)
                #pragma unroll
                for (int ni = 0; ni < 4; ni++) {
                    mma_bf(c[mi][ni], ah[mi], bh[ni]);
                    mma_bf(c[mi][ni], ah[mi], bl[ni]);
                    mma_bf(c[mi][ni], al[mi], bh[ni]);
                }
        }
        __syncthreads();
    }
    #undef FC_PREFETCH

    #pragma unroll
    for (int mi = 0; mi < 2; mi++)
        #pragma unroll
        for (int ni = 0; ni < 4; ni++) {
            int col = n0 + wn * 32 + ni * 8 + (lane & 3) * 2;
            #pragma unroll
            for (int half = 0; half < 2; half++) {
                int row = m0 + wm * 32 + mi * 16 + (lane >> 2) + half * 8;
                size_t off = (size_t)row * DMODEL + col;
                float2 r = *(const float2*)(qkv + off);
                *(float2*)(out + off) =
                    make_float2(c[mi][ni][half * 2] + r.x, c[mi][ni][half * 2 + 1] + r.y);
            }
        }
}

// ============================================================================
// LayerNorm in place.
// ============================================================================
__global__ __launch_bounds__(256)
void ln_kernel(float* __restrict__ out,
               const float* __restrict__ gamma,
               const float* __restrict__ beta)
{
    const size_t base = (size_t)blockIdx.x * DMODEL;
    const int tid = threadIdx.x;
    const int wid = tid >> 5, lane = tid & 31;

    float4 v = *(float4*)(out + base + (size_t)tid * 4);
    float s  = v.x + v.y + v.z + v.w;
    float sq = v.x * v.x + v.y * v.y + v.z * v.z + v.w * v.w;
    s  = warp_sum(s);
    sq = warp_sum(sq);
    __shared__ float rs[8], rq[8];
    if (lane == 0) { rs[wid] = s; rq[wid] = sq; }
    __syncthreads();
    float ts = (lane < 8) ? rs[lane] : 0.0f; ts = warp_sum(ts);
    float tq = (lane < 8) ? rq[lane] : 0.0f; tq = warp_sum(tq);

    float mean = ts * (1.0f / DMODEL);
    float var  = tq * (1.0f / DMODEL) - mean * mean;
    float inv  = rsqrtf(var + 1e-6f);

    float4 g  = *(const float4*)(gamma + tid * 4);
    float4 bt = *(const float4*)(beta + tid * 4);
    float4 o;
    o.x = (v.x - mean) * inv * g.x + bt.x;
    o.y = (v.y - mean) * inv * g.y + bt.y;
    o.z = (v.z - mean) * inv * g.z + bt.z;
    o.w = (v.w - mean) * inv * g.w + bt.w;
    *(float4*)(out + base + (size_t)tid * 4) = o;
}

// ============================================================================
extern "C" void kernel_launch(void* const* d_in, const int* in_sizes, int n_in,
                              void* d_out, int out_size)
{
    (void)in_sizes; (void)n_in; (void)out_size;
    const float* qkv  = (const float*)d_in[0];
    const int*   mask = (const int*)  d_in[1];
    const float* w_qs = (const float*)d_in[2];
    const float* w_ks = (const float*)d_in[3];
    const float* w_vs = (const float*)d_in[4];
    const float* w_fc = (const float*)d_in[5];
    const float* ln_g = (const float*)d_in[6];
    const float* ln_b = (const float*)d_in[7];

    float* out_main = (float*)d_out;
    float* attn     = (float*)d_out + OUT_ELEMS;

    static bool attr_set = false;
    if (!attr_set) {
        cudaFuncSetAttribute(gemm_qk,    cudaFuncAttributeMaxDynamicSharedMemorySize, QK_SMEM);
        cudaFuncSetAttribute(gemm_v,     cudaFuncAttributeMaxDynamicSharedMemorySize, V_SMEM);
        cudaFuncSetAttribute(gemm_fc,    cudaFuncAttributeMaxDynamicSharedMemorySize, QK_SMEM);
        cudaFuncSetAttribute(attn_fused, cudaFuncAttributeMaxDynamicSharedMemorySize, AF_SMEM);
        attr_set = true;
    }

    split_x   <<<BS * DMODEL / 4 / 256, 256>>>(qkv);
    wtrans    <<<dim3(32, 32, 4), 256>>>(w_qs, w_ks, w_vs, w_fc);
    gemm_qk   <<<dim3(NHEAD, BS / 128, 2), 256, QK_SMEM>>>();
    gemm_v    <<<dim3(NHEAD, BS / 128), 256, V_SMEM>>>();
    attn_fused<<<dim3(SEQ / 128, BATCH * NHEAD), 256, AF_SMEM>>>(mask, attn);
    norm_attn <<<(size_t)BATCH * NHEAD * SEQ * SEQ / 1024, 256>>>(attn);
    gemm_fc   <<<dim3(DMODEL / 64, BS / 128), 256, QK_SMEM>>>(qkv, out_main);
    ln_kernel <<<BS, 256>>>(out_main, ln_g, ln_b);
}

// round 7
// speedup vs baseline: 1.2088x; 1.2088x over previous
#include <cuda_runtime.h>
#include <cuda_bf16.h>
#include <cstdint>

#define NHEAD 16
#define DK 64
#define SEQ 2048
#define BATCH 2
#define DMODEL 1024
#define BS (BATCH*SEQ)

static const size_t OUT_ELEMS = (size_t)BATCH * SEQ * DMODEL;   // 4,194,304

// -------- scratch (static device globals; no runtime allocation) --------
__device__ __nv_bfloat16 g_xhi[(size_t)BS * DMODEL];
__device__ __nv_bfloat16 g_xlo[(size_t)BS * DMODEL];
__device__ __nv_bfloat16 g_wqt_hi[(size_t)DMODEL * DMODEL];
__device__ __nv_bfloat16 g_wqt_lo[(size_t)DMODEL * DMODEL];
__device__ __nv_bfloat16 g_wkt_hi[(size_t)DMODEL * DMODEL];
__device__ __nv_bfloat16 g_wkt_lo[(size_t)DMODEL * DMODEL];
__device__ __nv_bfloat16 g_wft_hi[(size_t)DMODEL * DMODEL];
__device__ __nv_bfloat16 g_wft_lo[(size_t)DMODEL * DMODEL];
__device__ __nv_bfloat16 g_wvt  [(size_t)DMODEL * DMODEL];
__device__ __nv_bfloat16 g_qhi[(size_t)BATCH * NHEAD * SEQ * DK];
__device__ __nv_bfloat16 g_qlo[(size_t)BATCH * NHEAD * SEQ * DK];
__device__ __nv_bfloat16 g_khi[(size_t)BATCH * NHEAD * SEQ * DK];
__device__ __nv_bfloat16 g_klo[(size_t)BATCH * NHEAD * SEQ * DK];
__device__ __nv_bfloat16 g_vp [(size_t)BATCH * NHEAD * SEQ * DK];
__device__ __nv_bfloat16 g_ohi[(size_t)BS * DMODEL];
__device__ __nv_bfloat16 g_olo[(size_t)BS * DMODEL];
__device__ float         g_psum[(size_t)BATCH * NHEAD * SEQ * 16];  // per-row, per-ktile exp sums

// ======================= warp-MMA helpers =======================
__device__ __forceinline__ uint32_t smem_u32(const void* p) {
    uint32_t a;
    asm("{ .reg .u64 t; cvta.to.shared.u64 t, %1; cvt.u32.u64 %0, t; }" : "=r"(a) : "l"(p));
    return a;
}
__device__ __forceinline__ void ldsm4(uint32_t* r, uint32_t addr) {
    asm volatile("ldmatrix.sync.aligned.m8n8.x4.shared.b16 {%0,%1,%2,%3}, [%4];"
                 : "=r"(r[0]), "=r"(r[1]), "=r"(r[2]), "=r"(r[3]) : "r"(addr));
}
__device__ __forceinline__ void ldsm2(uint32_t* r, uint32_t addr) {
    asm volatile("ldmatrix.sync.aligned.m8n8.x2.shared.b16 {%0,%1}, [%2];"
                 : "=r"(r[0]), "=r"(r[1]) : "r"(addr));
}
__device__ __forceinline__ void ldsm2t(uint32_t* r, uint32_t addr) {
    asm volatile("ldmatrix.sync.aligned.m8n8.x2.trans.shared.b16 {%0,%1}, [%2];"
                 : "=r"(r[0]), "=r"(r[1]) : "r"(addr));
}
__device__ __forceinline__ void mma_bf(float* c, const uint32_t* a, const uint32_t* b) {
    asm volatile(
        "mma.sync.aligned.m16n8k16.row.col.f32.bf16.bf16.f32 "
        "{%0,%1,%2,%3}, {%4,%5,%6,%7}, {%8,%9}, {%0,%1,%2,%3};"
        : "+f"(c[0]), "+f"(c[1]), "+f"(c[2]), "+f"(c[3])
        : "r"(a[0]), "r"(a[1]), "r"(a[2]), "r"(a[3]), "r"(b[0]), "r"(b[1]));
}
__device__ __forceinline__ uint32_t pack_bf2f(float a, float b) {
    __nv_bfloat162 h = __floats2bfloat162_rn(a, b);
    return *reinterpret_cast<uint32_t*>(&h);
}
__device__ __forceinline__ void split2(float v0, float v1, uint32_t& hi, uint32_t& lo) {
    __nv_bfloat16 h0 = __float2bfloat16(v0), h1 = __float2bfloat16(v1);
    __nv_bfloat16 l0 = __float2bfloat16(v0 - __bfloat162float(h0));
    __nv_bfloat16 l1 = __float2bfloat16(v1 - __bfloat162float(h1));
    __nv_bfloat162 hh; hh.x = h0; hh.y = h1;
    __nv_bfloat162 ll; ll.x = l0; ll.y = l1;
    hi = *reinterpret_cast<uint32_t*>(&hh);
    lo = *reinterpret_cast<uint32_t*>(&ll);
}
__device__ __forceinline__ float warp_sum(float v) {
    #pragma unroll
    for (int o = 16; o > 0; o >>= 1) v += __shfl_xor_sync(0xffffffffu, v, o);
    return v;
}

// ============================================================================
// prep 1: split qkv into bf16 hi/lo planes
// ============================================================================
__global__ __launch_bounds__(256)
void split_x(const float* __restrict__ x)
{
    size_t i = ((size_t)blockIdx.x * 256 + threadIdx.x) * 4;
    float4 v = *(const float4*)(x + i);
    uint32_t h0, l0, h1, l1;
    split2(v.x, v.y, h0, l0);
    split2(v.z, v.w, h1, l1);
    *(uint2*)(g_xhi + i) = make_uint2(h0, h1);
    *(uint2*)(g_xlo + i) = make_uint2(l0, l1);
}

// ============================================================================
// prep 2: transpose + split weights -> [n][k] bf16 planes
// ============================================================================
__global__ __launch_bounds__(256)
void wtrans(const float* __restrict__ wq, const float* __restrict__ wk,
            const float* __restrict__ wv, const float* __restrict__ wf)
{
    const int z = blockIdx.z;
    const float* W = (z == 0) ? wq : (z == 1) ? wk : (z == 2) ? wv : wf;
    __nv_bfloat16* Ohi = (z == 0) ? g_wqt_hi : (z == 1) ? g_wkt_hi : (z == 2) ? g_wvt : g_wft_hi;
    __nv_bfloat16* Olo = (z == 0) ? g_wqt_lo : (z == 1) ? g_wkt_lo : (z == 3) ? g_wft_lo : nullptr;

    __shared__ float t[32][33];
    const int n0 = blockIdx.x * 32, k0 = blockIdx.y * 32;
    const int tx = threadIdx.x & 31, ty = threadIdx.x >> 5;
    #pragma unroll
    for (int j = 0; j < 4; j++)
        t[ty + 8 * j][tx] = W[(size_t)(k0 + ty + 8 * j) * DMODEL + n0 + tx];
    __syncthreads();
    #pragma unroll
    for (int j = 0; j < 4; j++) {
        float v = t[tx][ty + 8 * j];
        __nv_bfloat16 h = __float2bfloat16(v);
        size_t off = (size_t)(n0 + ty + 8 * j) * DMODEL + k0 + tx;
        Ohi[off] = h;
        if (Olo) Olo[off] = __float2bfloat16(v - __bfloat162float(h));
    }
}

// ============================================================================
// GEMM Q/K projection (bf16x3) — R4 version (plain loads, measured good).
// ============================================================================
__global__ __launch_bounds__(256)
void gemm_qk()
{
    const int z = blockIdx.z;                  // 0=Q, 1=K
    const __nv_bfloat16* Whi = z ? g_wkt_hi : g_wqt_hi;
    const __nv_bfloat16* Wlo = z ? g_wkt_lo : g_wqt_lo;
    const int h  = blockIdx.x;
    const int n0 = h * 64;
    const int m0 = blockIdx.y * 128;

    __shared__ __align__(16) __nv_bfloat16 Ah[128 * 40], Al[128 * 40];
    __shared__ __align__(16) __nv_bfloat16 Bh[64 * 40],  Bl[64 * 40];

    const int tid = threadIdx.x;
    const int w = tid >> 5, lane = tid & 31;
    const int wm = w >> 1, wn = w & 1;

    const uint32_t uAh = smem_u32(Ah), uAl = smem_u32(Al);
    const uint32_t uBh = smem_u32(Bh), uBl = smem_u32(Bl);

    float c[2][4][4];
    #pragma unroll
    for (int mi = 0; mi < 2; mi++)
        #pragma unroll
        for (int ni = 0; ni < 4; ni++)
            #pragma unroll
            for (int r = 0; r < 4; r++) c[mi][ni][r] = 0.0f;

    for (int kc = 0; kc < 32; kc++) {
        const int k0 = kc * 32;
        #pragma unroll
        for (int t = 0; t < 2; t++) {
            int idx = tid + t * 256;
            int r = idx >> 2, cc = (idx & 3) * 8;
            *(uint4*)(Ah + r * 40 + cc) = *(const uint4*)(g_xhi + (size_t)(m0 + r) * DMODEL + k0 + cc);
            *(uint4*)(Al + r * 40 + cc) = *(const uint4*)(g_xlo + (size_t)(m0 + r) * DMODEL + k0 + cc);
        }
        {
            int r = tid >> 2, cc = (tid & 3) * 8;
            *(uint4*)(Bh + r * 40 + cc) = *(const uint4*)(Whi + (size_t)(n0 + r) * DMODEL + k0 + cc);
            *(uint4*)(Bl + r * 40 + cc) = *(const uint4*)(Wlo + (size_t)(n0 + r) * DMODEL + k0 + cc);
        }
        __syncthreads();
        #pragma unroll
        for (int ks = 0; ks < 2; ks++) {
            uint32_t ah[2][4], al[2][4], bh[4][2], bl[4][2];
            #pragma unroll
            for (int mi = 0; mi < 2; mi++) {
                uint32_t off = ((wm * 32 + mi * 16 + (lane & 15)) * 40 + (lane >> 4) * 8 + ks * 16) * 2;
                ldsm4(ah[mi], uAh + off);
                ldsm4(al[mi], uAl + off);
            }
            #pragma unroll
            for (int ni = 0; ni < 4; ni++) {
                uint32_t off = ((wn * 32 + ni * 8 + (lane & 7)) * 40 + ((lane >> 3) & 1) * 8 + ks * 16) * 2;
                ldsm2(bh[ni], uBh + off);
                ldsm2(bl[ni], uBl + off);
            }
            #pragma unroll
            for (int mi = 0; mi < 2; mi++)
                #pragma unroll
                for (int ni = 0; ni < 4; ni++) {
                    mma_bf(c[mi][ni], ah[mi], bh[ni]);
                    mma_bf(c[mi][ni], ah[mi], bl[ni]);
                    mma_bf(c[mi][ni], al[mi], bh[ni]);
                }
        }
        __syncthreads();
    }

    const float scale = z ? 1.0f : 0.125f;
    __nv_bfloat16* hiDst = z ? g_khi : g_qhi;
    __nv_bfloat16* loDst = z ? g_klo : g_qlo;
    #pragma unroll
    for (int mi = 0; mi < 2; mi++)
        #pragma unroll
        for (int ni = 0; ni < 4; ni++) {
            int col = wn * 32 + ni * 8 + (lane & 3) * 2;
            #pragma unroll
            for (int half = 0; half < 2; half++) {
                int row = m0 + wm * 32 + mi * 16 + (lane >> 2) + half * 8;
                int b = row >> 11, s = row & 2047;
                size_t off = ((size_t)((b * NHEAD + h) * SEQ + s)) * DK + col;
                uint32_t hi, lo;
                split2(c[mi][ni][half * 2] * scale, c[mi][ni][half * 2 + 1] * scale, hi, lo);
                *(uint32_t*)(hiDst + off) = hi;
                *(uint32_t*)(loDst + off) = lo;
            }
        }
}

// ============================================================================
// GEMM V projection (plain bf16) — R4 version.
// ============================================================================
__global__ __launch_bounds__(256)
void gemm_v()
{
    const int h  = blockIdx.x;
    const int n0 = h * 64;
    const int m0 = blockIdx.y * 128;

    __shared__ __align__(16) __nv_bfloat16 Ah[128 * 40];
    __shared__ __align__(16) __nv_bfloat16 Bh[64 * 40];

    const int tid = threadIdx.x;
    const int w = tid >> 5, lane = tid & 31;
    const int wm = w >> 1, wn = w & 1;
    const uint32_t uAh = smem_u32(Ah), uBh = smem_u32(Bh);

    float c[2][4][4];
    #pragma unroll
    for (int mi = 0; mi < 2; mi++)
        #pragma unroll
        for (int ni = 0; ni < 4; ni++)
            #pragma unroll
            for (int r = 0; r < 4; r++) c[mi][ni][r] = 0.0f;

    for (int kc = 0; kc < 32; kc++) {
        const int k0 = kc * 32;
        #pragma unroll
        for (int t = 0; t < 2; t++) {
            int idx = tid + t * 256;
            int r = idx >> 2, cc = (idx & 3) * 8;
            *(uint4*)(Ah + r * 40 + cc) = *(const uint4*)(g_xhi + (size_t)(m0 + r) * DMODEL + k0 + cc);
        }
        {
            int r = tid >> 2, cc = (tid & 3) * 8;
            *(uint4*)(Bh + r * 40 + cc) = *(const uint4*)(g_wvt + (size_t)(n0 + r) * DMODEL + k0 + cc);
        }
        __syncthreads();
        #pragma unroll
        for (int ks = 0; ks < 2; ks++) {
            uint32_t ah[2][4], bh[4][2];
            #pragma unroll
            for (int mi = 0; mi < 2; mi++)
                ldsm4(ah[mi], uAh + ((wm * 32 + mi * 16 + (lane & 15)) * 40 + (lane >> 4) * 8 + ks * 16) * 2);
            #pragma unroll
            for (int ni = 0; ni < 4; ni++)
                ldsm2(bh[ni], uBh + ((wn * 32 + ni * 8 + (lane & 7)) * 40 + ((lane >> 3) & 1) * 8 + ks * 16) * 2);
            #pragma unroll
            for (int mi = 0; mi < 2; mi++)
                #pragma unroll
                for (int ni = 0; ni < 4; ni++)
                    mma_bf(c[mi][ni], ah[mi], bh[ni]);
        }
        __syncthreads();
    }

    #pragma unroll
    for (int mi = 0; mi < 2; mi++)
        #pragma unroll
        for (int ni = 0; ni < 4; ni++) {
            int col = wn * 32 + ni * 8 + (lane & 3) * 2;
            #pragma unroll
            for (int half = 0; half < 2; half++) {
                int row = m0 + wm * 32 + mi * 16 + (lane >> 2) + half * 8;
                int b = row >> 11, s = row & 2047;
                size_t off = ((size_t)((b * NHEAD + h) * SEQ + s)) * DK + col;
                *(uint32_t*)(g_vp + off) =
                    pack_bf2f(c[mi][ni][half * 2], c[mi][ni][half * 2 + 1]);
            }
        }
}

// ============================================================================
// Scores (bf16x3) + mask + exp epilogue.  Writes UNNORMALIZED exp to attn and
// deterministic per-(row, ktile) partial sums to g_psum.
// CTA 128x128, 8 warps (2m x 4n).
// ============================================================================
static constexpr int SC_T = 128 * 72;
static constexpr int SC_BYTES = 4 * SC_T * 2;            // 73728

__global__ __launch_bounds__(256)
void scores_mm(const int* __restrict__ mask, float* __restrict__ attn)
{
    extern __shared__ __align__(16) __nv_bfloat16 smem[];
    __nv_bfloat16* sQh = smem;
    __nv_bfloat16* sQl = smem + SC_T;
    __nv_bfloat16* sKh = smem + 2 * SC_T;
    __nv_bfloat16* sKl = smem + 3 * SC_T;
    __shared__ float rsum_sm[128][4];

    const int tid = threadIdx.x;
    const int w = tid >> 5, lane = tid & 31;
    const int wm = w >> 2, wn = w & 3;       // 2 x 4
    const int kt = blockIdx.x;
    const int k0 = kt * 128;
    const int q0 = blockIdx.y * 128;
    const int bh = blockIdx.z;
    const int b  = bh >> 4;

    const size_t plane = (size_t)bh * SEQ * DK;
    const __nv_bfloat16* srcs[4] = {
        g_qhi + plane + (size_t)q0 * DK, g_qlo + plane + (size_t)q0 * DK,
        g_khi + plane + (size_t)k0 * DK, g_klo + plane + (size_t)k0 * DK };
    __nv_bfloat16* dsts[4] = { sQh, sQl, sKh, sKl };
    #pragma unroll
    for (int t = 0; t < 4; t++)
        for (int idx = tid; idx < 1024; idx += 256) {
            int r = idx >> 3, cc = (idx & 7) * 8;
            *(uint4*)(dsts[t] + r * 72 + cc) = *(const uint4*)(srcs[t] + (size_t)r * DK + cc);
        }
    __syncthreads();

    const uint32_t uQh = smem_u32(sQh), uQl = smem_u32(sQl);
    const uint32_t uKh = smem_u32(sKh), uKl = smem_u32(sKl);

    float c[4][4][4];
    #pragma unroll
    for (int mi = 0; mi < 4; mi++)
        #pragma unroll
        for (int ni = 0; ni < 4; ni++)
            #pragma unroll
            for (int r = 0; r < 4; r++) c[mi][ni][r] = 0.0f;

    #pragma unroll
    for (int pass = 0; pass < 3; pass++) {
        const uint32_t uA = (pass == 2) ? uQl : uQh;
        const uint32_t uB = (pass == 1) ? uKl : uKh;
        #pragma unroll
        for (int ks = 0; ks < 4; ks++) {
            uint32_t a[4][4], bf[4][2];
            #pragma unroll
            for (int mi = 0; mi < 4; mi++)
                ldsm4(a[mi], uA + ((wm * 64 + mi * 16 + (lane & 15)) * 72 + (lane >> 4) * 8 + ks * 16) * 2);
            #pragma unroll
            for (int ni = 0; ni < 4; ni++)
                ldsm2(bf[ni], uB + ((wn * 32 + ni * 8 + (lane & 7)) * 72 + ((lane >> 3) & 1) * 8 + ks * 16) * 2);
            #pragma unroll
            for (int mi = 0; mi < 4; mi++)
                #pragma unroll
                for (int ni = 0; ni < 4; ni++)
                    mma_bf(c[mi][ni], a[mi], bf[ni]);
        }
    }

    // ---- epilogue: mask + exp (unnormalized) + write + rowsum partials ----
    float* aplane = attn + (size_t)bh * SEQ * SEQ;
    const int* mplane = mask + (size_t)b * SEQ * SEQ;
    float rowsum[4][2];
    #pragma unroll
    for (int mi = 0; mi < 4; mi++) { rowsum[mi][0] = 0.0f; rowsum[mi][1] = 0.0f; }

    #pragma unroll
    for (int mi = 0; mi < 4; mi++)
        #pragma unroll
        for (int ni = 0; ni < 4; ni++) {
            int kcol = k0 + wn * 32 + ni * 8 + (lane & 3) * 2;
            #pragma unroll
            for (int half = 0; half < 2; half++) {
                int qrow = q0 + wm * 64 + mi * 16 + (lane >> 2) + half * 8;
                size_t off = (size_t)qrow * SEQ + kcol;
                int2 mv = *(const int2*)(mplane + off);
                float e0 = mv.x ? __expf(fminf(c[mi][ni][half * 2],     80.0f)) : 0.0f;
                float e1 = mv.y ? __expf(fminf(c[mi][ni][half * 2 + 1], 80.0f)) : 0.0f;
                rowsum[mi][half] += e0 + e1;
                *(float2*)(aplane + off) = make_float2(e0, e1);
            }
        }

    // reduce across quad lanes (lane&3) then across wn warps
    #pragma unroll
    for (int mi = 0; mi < 4; mi++)
        #pragma unroll
        for (int half = 0; half < 2; half++) {
            float v = rowsum[mi][half];
            v += __shfl_xor_sync(0xffffffffu, v, 1);
            v += __shfl_xor_sync(0xffffffffu, v, 2);
            if ((lane & 3) == 0)
                rsum_sm[wm * 64 + mi * 16 + (lane >> 2) + half * 8][wn] = v;
        }
    __syncthreads();
    if (tid < 128) {
        float s = rsum_sm[tid][0] + rsum_sm[tid][1] + rsum_sm[tid][2] + rsum_sm[tid][3];
        g_psum[((size_t)bh * SEQ + q0 + tid) * 16 + kt] = s;
    }
}

// ============================================================================
// PV (plain bf16): reads UNNORMALIZED fp32 exp attn, normalizes with rinv
// (from g_psum), writes normalized attn back, and computes O = Pnorm @ V.
// CTA 128q x 64d, 8 warps (4m x 2n), k-chunk 64.
// ============================================================================
__global__ __launch_bounds__(256)
void pv_mm(float* __restrict__ attn)
{
    __shared__ __align__(16) __nv_bfloat16 Ps[128 * 72];
    __shared__ __align__(16) __nv_bfloat16 Vs[64 * 72];
    __shared__ float inv_s[128];

    const int tid = threadIdx.x;
    const int w = tid >> 5, lane = tid & 31;
    const int wm = w >> 1, wn = w & 1;       // 4 x 2
    const int q0 = blockIdx.x * 128;
    const int bh = blockIdx.y;
    const int b  = bh >> 4, h = bh & 15;

    // per-row 1/sum from deterministic partials
    if (tid < 128) {
        const float* ps = g_psum + ((size_t)bh * SEQ + q0 + tid) * 16;
        float s = 0.0f;
        #pragma unroll
        for (int k = 0; k < 16; k++) s += ps[k];
        inv_s[tid] = 1.0f / s;
    }
    __syncthreads();

    const uint32_t uP = smem_u32(Ps), uV = smem_u32(Vs);
    float* ap = attn + (size_t)bh * SEQ * SEQ + (size_t)q0 * SEQ;
    const __nv_bfloat16* vp = g_vp + (size_t)bh * SEQ * DK;

    float c[2][4][4];
    #pragma unroll
    for (int mi = 0; mi < 2; mi++)
        #pragma unroll
        for (int ni = 0; ni < 4; ni++)
            #pragma unroll
            for (int r = 0; r < 4; r++) c[mi][ni][r] = 0.0f;

    for (int kc = 0; kc < 32; kc++) {
        const int s0 = kc * 64;
        // P tile: 128 rows x 64 fp32 -> normalize, write back, bf16 to smem
        #pragma unroll
        for (int t = 0; t < 8; t++) {
            int idx = tid + t * 256;
            int r = idx >> 4, c4 = (idx & 15) * 4;
            const float inv = inv_s[r];
            float4 v = *(const float4*)(ap + (size_t)r * SEQ + s0 + c4);
            v.x *= inv; v.y *= inv; v.z *= inv; v.w *= inv;
            *(float4*)(ap + (size_t)r * SEQ + s0 + c4) = v;
            *(uint2*)(Ps + r * 72 + c4) = make_uint2(pack_bf2f(v.x, v.y), pack_bf2f(v.z, v.w));
        }
        #pragma unroll
        for (int t = 0; t < 2; t++) {
            int idx = tid + t * 256;
            int r = idx >> 3, cc = (idx & 7) * 8;
            *(uint4*)(Vs + r * 72 + cc) = *(const uint4*)(vp + (size_t)(s0 + r) * DK + cc);
        }
        __syncthreads();
        #pragma unroll
        for (int ks = 0; ks < 4; ks++) {
            uint32_t a[2][4], bf[4][2];
            #pragma unroll
            for (int mi = 0; mi < 2; mi++)
                ldsm4(a[mi], uP + ((wm * 32 + mi * 16 + (lane & 15)) * 72 + (lane >> 4) * 8 + ks * 16) * 2);
            #pragma unroll
            for (int ni = 0; ni < 4; ni++)
                ldsm2t(bf[ni], uV + ((ks * 16 + (lane & 15)) * 72 + wn * 32 + ni * 8) * 2);
            #pragma unroll
            for (int mi = 0; mi < 2; mi++)
                #pragma unroll
                for (int ni = 0; ni < 4; ni++)
                    mma_bf(c[mi][ni], a[mi], bf[ni]);
        }
        __syncthreads();
    }

    #pragma unroll
    for (int mi = 0; mi < 2; mi++)
        #pragma unroll
        for (int ni = 0; ni < 4; ni++) {
            int d = wn * 32 + ni * 8 + (lane & 3) * 2;
            #pragma unroll
            for (int half = 0; half < 2; half++) {
                int s = q0 + wm * 32 + mi * 16 + (lane >> 2) + half * 8;
                size_t off = (size_t)(b * SEQ + s) * DMODEL + h * DK + d;
                uint32_t hi, lo;
                split2(c[mi][ni][half * 2], c[mi][ni][half * 2 + 1], hi, lo);
                *(uint32_t*)(g_ohi + off) = hi;
                *(uint32_t*)(g_olo + off) = lo;
            }
        }
}

// ============================================================================
// FC (bf16x3) + residual — R4 version.
// ============================================================================
__global__ __launch_bounds__(256)
void gemm_fc(const float* __restrict__ qkv, float* __restrict__ out)
{
    const int n0 = blockIdx.x * 64;
    const int m0 = blockIdx.y * 128;

    __shared__ __align__(16) __nv_bfloat16 Ah[128 * 40], Al[128 * 40];
    __shared__ __align__(16) __nv_bfloat16 Bh[64 * 40],  Bl[64 * 40];

    const int tid = threadIdx.x;
    const int w = tid >> 5, lane = tid & 31;
    const int wm = w >> 1, wn = w & 1;
    const uint32_t uAh = smem_u32(Ah), uAl = smem_u32(Al);
    const uint32_t uBh = smem_u32(Bh), uBl = smem_u32(Bl);

    float c[2][4][4];
    #pragma unroll
    for (int mi = 0; mi < 2; mi++)
        #pragma unroll
        for (int ni = 0; ni < 4; ni++)
            #pragma unroll
            for (int r = 0; r < 4; r++) c[mi][ni][r] = 0.0f;

    for (int kc = 0; kc < 32; kc++) {
        const int k0 = kc * 32;
        #pragma unroll
        for (int t = 0; t < 2; t++) {
            int idx = tid + t * 256;
            int r = idx >> 2, cc = (idx & 3) * 8;
            *(uint4*)(Ah + r * 40 + cc) = *(const uint4*)(g_ohi + (size_t)(m0 + r) * DMODEL + k0 + cc);
            *(uint4*)(Al + r * 40 + cc) = *(const uint4*)(g_olo + (size_t)(m0 + r) * DMODEL + k0 + cc);
        }
        {
            int r = tid >> 2, cc = (tid & 3) * 8;
            *(uint4*)(Bh + r * 40 + cc) = *(const uint4*)(g_wft_hi + (size_t)(n0 + r) * DMODEL + k0 + cc);
            *(uint4*)(Bl + r * 40 + cc) = *(const uint4*)(g_wft_lo + (size_t)(n0 + r) * DMODEL + k0 + cc);
        }
        __syncthreads();
        #pragma unroll
        for (int ks = 0; ks < 2; ks++) {
            uint32_t ah[2][4], al[2][4], bh[4][2], bl[4][2];
            #pragma unroll
            for (int mi = 0; mi < 2; mi++) {
                uint32_t off = ((wm * 32 + mi * 16 + (lane & 15)) * 40 + (lane >> 4) * 8 + ks * 16) * 2;
                ldsm4(ah[mi], uAh + off);
                ldsm4(al[mi], uAl + off);
            }
            #pragma unroll
            for (int ni = 0; ni < 4; ni++) {
                uint32_t off = ((wn * 32 + ni * 8 + (lane & 7)) * 40 + ((lane >> 3) & 1) * 8 + ks * 16) * 2;
                ldsm2(bh[ni], uBh + off);
                ldsm2(bl[ni], uBl + off);
            }
            #pragma unroll
            for (int mi = 0; mi < 2; mi++)
                #pragma unroll
                for (int ni = 0; ni < 4; ni++) {
                    mma_bf(c[mi][ni], ah[mi], bh[ni]);
                    mma_bf(c[mi][ni], ah[mi], bl[ni]);
                    mma_bf(c[mi][ni], al[mi], bh[ni]);
                }
        }
        __syncthreads();
    }

    #pragma unroll
    for (int mi = 0; mi < 2; mi++)
        #pragma unroll
        for (int ni = 0; ni < 4; ni++) {
            int col = n0 + wn * 32 + ni * 8 + (lane & 3) * 2;
            #pragma unroll
            for (int half = 0; half < 2; half++) {
                int row = m0 + wm * 32 + mi * 16 + (lane >> 2) + half * 8;
                size_t off = (size_t)row * DMODEL + col;
                float2 r = *(const float2*)(qkv + off);
                *(float2*)(out + off) =
                    make_float2(c[mi][ni][half * 2] + r.x, c[mi][ni][half * 2 + 1] + r.y);
            }
        }
}

// ============================================================================
// LayerNorm in place.
// ============================================================================
__global__ __launch_bounds__(256)
void ln_kernel(float* __restrict__ out,
               const float* __restrict__ gamma,
               const float* __restrict__ beta)
{
    const size_t base = (size_t)blockIdx.x * DMODEL;
    const int tid = threadIdx.x;
    const int wid = tid >> 5, lane = tid & 31;

    float4 v = *(float4*)(out + base + (size_t)tid * 4);
    float s  = v.x + v.y + v.z + v.w;
    float sq = v.x * v.x + v.y * v.y + v.z * v.z + v.w * v.w;
    s  = warp_sum(s);
    sq = warp_sum(sq);
    __shared__ float rs[8], rq[8];
    if (lane == 0) { rs[wid] = s; rq[wid] = sq; }
    __syncthreads();
    float ts = (lane < 8) ? rs[lane] : 0.0f; ts = warp_sum(ts);
    float tq = (lane < 8) ? rq[lane] : 0.0f; tq = warp_sum(tq);

    float mean = ts * (1.0f / DMODEL);
    float var  = tq * (1.0f / DMODEL) - mean * mean;
    float inv  = rsqrtf(var + 1e-6f);

    float4 g  = *(const float4*)(gamma + tid * 4);
    float4 bt = *(const float4*)(beta + tid * 4);
    float4 o;
    o.x = (v.x - mean) * inv * g.x + bt.x;
    o.y = (v.y - mean) * inv * g.y + bt.y;
    o.z = (v.z - mean) * inv * g.z + bt.z;
    o.w = (v.w - mean) * inv * g.w + bt.w;
    *(float4*)(out + base + (size_t)tid * 4) = o;
}

// ============================================================================
extern "C" void kernel_launch(void* const* d_in, const int* in_sizes, int n_in,
                              void* d_out, int out_size)
{
    (void)in_sizes; (void)n_in; (void)out_size;
    const float* qkv  = (const float*)d_in[0];
    const int*   mask = (const int*)  d_in[1];
    const float* w_qs = (const float*)d_in[2];
    const float* w_ks = (const float*)d_in[3];
    const float* w_vs = (const float*)d_in[4];
    const float* w_fc = (const float*)d_in[5];
    const float* ln_g = (const float*)d_in[6];
    const float* ln_b = (const float*)d_in[7];

    float* out_main = (float*)d_out;
    float* attn     = (float*)d_out + OUT_ELEMS;

    static bool attr_set = false;
    if (!attr_set) {
        cudaFuncSetAttribute(scores_mm, cudaFuncAttributeMaxDynamicSharedMemorySize, SC_BYTES);
        attr_set = true;
    }

    split_x   <<<BS * DMODEL / 4 / 256, 256>>>(qkv);
    wtrans    <<<dim3(32, 32, 4), 256>>>(w_qs, w_ks, w_vs, w_fc);
    gemm_qk   <<<dim3(NHEAD, BS / 128, 2), 256>>>();
    gemm_v    <<<dim3(NHEAD, BS / 128), 256>>>();
    scores_mm <<<dim3(SEQ / 128, SEQ / 128, BATCH * NHEAD), 256, SC_BYTES>>>(mask, attn);
    pv_mm     <<<dim3(SEQ / 128, BATCH * NHEAD), 256>>>(attn);
    gemm_fc   <<<dim3(DMODEL / 64, BS / 128), 256>>>(qkv, out_main);
    ln_kernel <<<BS, 256>>>(out_main, ln_g, ln_b);
}

// round 8
// speedup vs baseline: 1.4999x; 1.2409x over previous
#include <cuda_runtime.h>
#include <cuda_bf16.h>
#include <cstdint>

#define NHEAD 16
#define DK 64
#define SEQ 2048
#define BATCH 2
#define DMODEL 1024
#define BS (BATCH*SEQ)
#define NEGV -1000000000.0f

static const size_t OUT_ELEMS = (size_t)BATCH * SEQ * DMODEL;   // 4,194,304

// -------- scratch (static device globals; no runtime allocation) --------
__device__ __nv_bfloat16 g_xhi[(size_t)BS * DMODEL];
__device__ __nv_bfloat16 g_xlo[(size_t)BS * DMODEL];
__device__ __nv_bfloat16 g_wqt_hi[(size_t)DMODEL * DMODEL];
__device__ __nv_bfloat16 g_wqt_lo[(size_t)DMODEL * DMODEL];
__device__ __nv_bfloat16 g_wkt_hi[(size_t)DMODEL * DMODEL];
__device__ __nv_bfloat16 g_wkt_lo[(size_t)DMODEL * DMODEL];
__device__ __nv_bfloat16 g_wft_hi[(size_t)DMODEL * DMODEL];
__device__ __nv_bfloat16 g_wft_lo[(size_t)DMODEL * DMODEL];
__device__ __nv_bfloat16 g_wvt  [(size_t)DMODEL * DMODEL];
__device__ __nv_bfloat16 g_qhi[(size_t)BATCH * NHEAD * SEQ * DK];
__device__ __nv_bfloat16 g_qlo[(size_t)BATCH * NHEAD * SEQ * DK];
__device__ __nv_bfloat16 g_khi[(size_t)BATCH * NHEAD * SEQ * DK];
__device__ __nv_bfloat16 g_klo[(size_t)BATCH * NHEAD * SEQ * DK];
__device__ __nv_bfloat16 g_vp [(size_t)BATCH * NHEAD * SEQ * DK];
__device__ __nv_bfloat16 g_pb [(size_t)BATCH * NHEAD * SEQ * SEQ];  // bf16 softmax P
__device__ __nv_bfloat16 g_ohi[(size_t)BS * DMODEL];
__device__ __nv_bfloat16 g_olo[(size_t)BS * DMODEL];

// ======================= warp-MMA helpers =======================
__device__ __forceinline__ uint32_t smem_u32(const void* p) {
    uint32_t a;
    asm("{ .reg .u64 t; cvta.to.shared.u64 t, %1; cvt.u32.u64 %0, t; }" : "=r"(a) : "l"(p));
    return a;
}
__device__ __forceinline__ void ldsm4(uint32_t* r, uint32_t addr) {
    asm volatile("ldmatrix.sync.aligned.m8n8.x4.shared.b16 {%0,%1,%2,%3}, [%4];"
                 : "=r"(r[0]), "=r"(r[1]), "=r"(r[2]), "=r"(r[3]) : "r"(addr));
}
__device__ __forceinline__ void ldsm2(uint32_t* r, uint32_t addr) {
    asm volatile("ldmatrix.sync.aligned.m8n8.x2.shared.b16 {%0,%1}, [%2];"
                 : "=r"(r[0]), "=r"(r[1]) : "r"(addr));
}
__device__ __forceinline__ void ldsm2t(uint32_t* r, uint32_t addr) {
    asm volatile("ldmatrix.sync.aligned.m8n8.x2.trans.shared.b16 {%0,%1}, [%2];"
                 : "=r"(r[0]), "=r"(r[1]) : "r"(addr));
}
__device__ __forceinline__ void mma_bf(float* c, const uint32_t* a, const uint32_t* b) {
    asm volatile(
        "mma.sync.aligned.m16n8k16.row.col.f32.bf16.bf16.f32 "
        "{%0,%1,%2,%3}, {%4,%5,%6,%7}, {%8,%9}, {%0,%1,%2,%3};"
        : "+f"(c[0]), "+f"(c[1]), "+f"(c[2]), "+f"(c[3])
        : "r"(a[0]), "r"(a[1]), "r"(a[2]), "r"(a[3]), "r"(b[0]), "r"(b[1]));
}
__device__ __forceinline__ uint32_t pack_bf2f(float a, float b) {
    __nv_bfloat162 h = __floats2bfloat162_rn(a, b);
    return *reinterpret_cast<uint32_t*>(&h);
}
__device__ __forceinline__ void split2(float v0, float v1, uint32_t& hi, uint32_t& lo) {
    __nv_bfloat16 h0 = __float2bfloat16(v0), h1 = __float2bfloat16(v1);
    __nv_bfloat16 l0 = __float2bfloat16(v0 - __bfloat162float(h0));
    __nv_bfloat16 l1 = __float2bfloat16(v1 - __bfloat162float(h1));
    __nv_bfloat162 hh; hh.x = h0; hh.y = h1;
    __nv_bfloat162 ll; ll.x = l0; ll.y = l1;
    hi = *reinterpret_cast<uint32_t*>(&hh);
    lo = *reinterpret_cast<uint32_t*>(&ll);
}
__device__ __forceinline__ float warp_sum(float v) {
    #pragma unroll
    for (int o = 16; o > 0; o >>= 1) v += __shfl_xor_sync(0xffffffffu, v, o);
    return v;
}

// ============================================================================
// prep 1: split qkv into bf16 hi/lo planes
// ============================================================================
__global__ __launch_bounds__(256)
void split_x(const float* __restrict__ x)
{
    size_t i = ((size_t)blockIdx.x * 256 + threadIdx.x) * 4;
    float4 v = *(const float4*)(x + i);
    uint32_t h0, l0, h1, l1;
    split2(v.x, v.y, h0, l0);
    split2(v.z, v.w, h1, l1);
    *(uint2*)(g_xhi + i) = make_uint2(h0, h1);
    *(uint2*)(g_xlo + i) = make_uint2(l0, l1);
}

// ============================================================================
// prep 2: transpose + split weights -> [n][k] bf16 planes
// ============================================================================
__global__ __launch_bounds__(256)
void wtrans(const float* __restrict__ wq, const float* __restrict__ wk,
            const float* __restrict__ wv, const float* __restrict__ wf)
{
    const int z = blockIdx.z;
    const float* W = (z == 0) ? wq : (z == 1) ? wk : (z == 2) ? wv : wf;
    __nv_bfloat16* Ohi = (z == 0) ? g_wqt_hi : (z == 1) ? g_wkt_hi : (z == 2) ? g_wvt : g_wft_hi;
    __nv_bfloat16* Olo = (z == 0) ? g_wqt_lo : (z == 1) ? g_wkt_lo : (z == 3) ? g_wft_lo : nullptr;

    __shared__ float t[32][33];
    const int n0 = blockIdx.x * 32, k0 = blockIdx.y * 32;
    const int tx = threadIdx.x & 31, ty = threadIdx.x >> 5;
    #pragma unroll
    for (int j = 0; j < 4; j++)
        t[ty + 8 * j][tx] = W[(size_t)(k0 + ty + 8 * j) * DMODEL + n0 + tx];
    __syncthreads();
    #pragma unroll
    for (int j = 0; j < 4; j++) {
        float v = t[tx][ty + 8 * j];
        __nv_bfloat16 h = __float2bfloat16(v);
        size_t off = (size_t)(n0 + ty + 8 * j) * DMODEL + k0 + tx;
        Ohi[off] = h;
        if (Olo) Olo[off] = __float2bfloat16(v - __bfloat162float(h));
    }
}

// ============================================================================
// GEMM Q/K projection (bf16x3) with register-prefetch double buffering.
// CTA 128x64, 8 warps (4m x 2n), k-chunk 32.
// ============================================================================
__global__ __launch_bounds__(256)
void gemm_qk()
{
    const int z = blockIdx.z;                  // 0=Q, 1=K
    const __nv_bfloat16* Whi = z ? g_wkt_hi : g_wqt_hi;
    const __nv_bfloat16* Wlo = z ? g_wkt_lo : g_wqt_lo;
    const int h  = blockIdx.x;
    const int n0 = h * 64;
    const int m0 = blockIdx.y * 128;

    __shared__ __align__(16) __nv_bfloat16 Ah[128 * 40], Al[128 * 40];
    __shared__ __align__(16) __nv_bfloat16 Bh[64 * 40],  Bl[64 * 40];

    const int tid = threadIdx.x;
    const int w = tid >> 5, lane = tid & 31;
    const int wm = w >> 1, wn = w & 1;

    const uint32_t uAh = smem_u32(Ah), uAl = smem_u32(Al);
    const uint32_t uBh = smem_u32(Bh), uBl = smem_u32(Bl);

    const int ar0 = tid >> 2,        ac = (tid & 3) * 8;        // A row (plane part 0)
    const int ar1 = (tid + 256) >> 2;                           // A row (part 1)
    const int br  = tid >> 2,        bc = (tid & 3) * 8;        // B row

    float c[2][4][4];
    #pragma unroll
    for (int mi = 0; mi < 2; mi++)
        #pragma unroll
        for (int ni = 0; ni < 4; ni++)
            #pragma unroll
            for (int r = 0; r < 4; r++) c[mi][ni][r] = 0.0f;

    uint4 pAh0, pAh1, pAl0, pAl1, pBh, pBl;
    #define QK_LDG(KC) do { const int _k0 = (KC) * 32;                                   \
        pAh0 = *(const uint4*)(g_xhi + (size_t)(m0 + ar0) * DMODEL + _k0 + ac);          \
        pAh1 = *(const uint4*)(g_xhi + (size_t)(m0 + ar1) * DMODEL + _k0 + ac);          \
        pAl0 = *(const uint4*)(g_xlo + (size_t)(m0 + ar0) * DMODEL + _k0 + ac);          \
        pAl1 = *(const uint4*)(g_xlo + (size_t)(m0 + ar1) * DMODEL + _k0 + ac);          \
        pBh  = *(const uint4*)(Whi   + (size_t)(n0 + br)  * DMODEL + _k0 + bc);          \
        pBl  = *(const uint4*)(Wlo   + (size_t)(n0 + br)  * DMODEL + _k0 + bc);          \
    } while (0)

    QK_LDG(0);
    for (int kc = 0; kc < 32; kc++) {
        __syncthreads();
        *(uint4*)(Ah + ar0 * 40 + ac) = pAh0;
        *(uint4*)(Ah + ar1 * 40 + ac) = pAh1;
        *(uint4*)(Al + ar0 * 40 + ac) = pAl0;
        *(uint4*)(Al + ar1 * 40 + ac) = pAl1;
        *(uint4*)(Bh + br * 40 + bc) = pBh;
        *(uint4*)(Bl + br * 40 + bc) = pBl;
        __syncthreads();
        if (kc < 31) QK_LDG(kc + 1);

        #pragma unroll
        for (int ks = 0; ks < 2; ks++) {
            uint32_t ah[2][4], al[2][4], bh[4][2], bl[4][2];
            #pragma unroll
            for (int mi = 0; mi < 2; mi++) {
                uint32_t off = ((wm * 32 + mi * 16 + (lane & 15)) * 40 + (lane >> 4) * 8 + ks * 16) * 2;
                ldsm4(ah[mi], uAh + off);
                ldsm4(al[mi], uAl + off);
            }
            #pragma unroll
            for (int ni = 0; ni < 4; ni++) {
                uint32_t off = ((wn * 32 + ni * 8 + (lane & 7)) * 40 + ((lane >> 3) & 1) * 8 + ks * 16) * 2;
                ldsm2(bh[ni], uBh + off);
                ldsm2(bl[ni], uBl + off);
            }
            #pragma unroll
            for (int mi = 0; mi < 2; mi++)
                #pragma unroll
                for (int ni = 0; ni < 4; ni++) {
                    mma_bf(c[mi][ni], ah[mi], bh[ni]);
                    mma_bf(c[mi][ni], ah[mi], bl[ni]);
                    mma_bf(c[mi][ni], al[mi], bh[ni]);
                }
        }
    }
    #undef QK_LDG

    const float scale = z ? 1.0f : 0.125f;
    __nv_bfloat16* hiDst = z ? g_khi : g_qhi;
    __nv_bfloat16* loDst = z ? g_klo : g_qlo;
    #pragma unroll
    for (int mi = 0; mi < 2; mi++)
        #pragma unroll
        for (int ni = 0; ni < 4; ni++) {
            int col = wn * 32 + ni * 8 + (lane & 3) * 2;
            #pragma unroll
            for (int half = 0; half < 2; half++) {
                int row = m0 + wm * 32 + mi * 16 + (lane >> 2) + half * 8;
                int b = row >> 11, s = row & 2047;
                size_t off = ((size_t)((b * NHEAD + h) * SEQ + s)) * DK + col;
                uint32_t hi, lo;
                split2(c[mi][ni][half * 2] * scale, c[mi][ni][half * 2 + 1] * scale, hi, lo);
                *(uint32_t*)(hiDst + off) = hi;
                *(uint32_t*)(loDst + off) = lo;
            }
        }
}

// ============================================================================
// GEMM V projection (plain bf16) with register prefetch.
// ============================================================================
__global__ __launch_bounds__(256)
void gemm_v()
{
    const int h  = blockIdx.x;
    const int n0 = h * 64;
    const int m0 = blockIdx.y * 128;

    __shared__ __align__(16) __nv_bfloat16 Ah[128 * 40];
    __shared__ __align__(16) __nv_bfloat16 Bh[64 * 40];

    const int tid = threadIdx.x;
    const int w = tid >> 5, lane = tid & 31;
    const int wm = w >> 1, wn = w & 1;
    const uint32_t uAh = smem_u32(Ah), uBh = smem_u32(Bh);

    const int ar0 = tid >> 2, ac = (tid & 3) * 8;
    const int ar1 = (tid + 256) >> 2;

    float c[2][4][4];
    #pragma unroll
    for (int mi = 0; mi < 2; mi++)
        #pragma unroll
        for (int ni = 0; ni < 4; ni++)
            #pragma unroll
            for (int r = 0; r < 4; r++) c[mi][ni][r] = 0.0f;

    uint4 pA0, pA1, pB;
    #define V_LDG(KC) do { const int _k0 = (KC) * 32;                                    \
        pA0 = *(const uint4*)(g_xhi + (size_t)(m0 + ar0) * DMODEL + _k0 + ac);           \
        pA1 = *(const uint4*)(g_xhi + (size_t)(m0 + ar1) * DMODEL + _k0 + ac);           \
        pB  = *(const uint4*)(g_wvt + (size_t)(n0 + ar0) * DMODEL + _k0 + ac);           \
    } while (0)

    V_LDG(0);
    for (int kc = 0; kc < 32; kc++) {
        __syncthreads();
        *(uint4*)(Ah + ar0 * 40 + ac) = pA0;
        *(uint4*)(Ah + ar1 * 40 + ac) = pA1;
        *(uint4*)(Bh + ar0 * 40 + ac) = pB;
        __syncthreads();
        if (kc < 31) V_LDG(kc + 1);

        #pragma unroll
        for (int ks = 0; ks < 2; ks++) {
            uint32_t ah[2][4], bh[4][2];
            #pragma unroll
            for (int mi = 0; mi < 2; mi++)
                ldsm4(ah[mi], uAh + ((wm * 32 + mi * 16 + (lane & 15)) * 40 + (lane >> 4) * 8 + ks * 16) * 2);
            #pragma unroll
            for (int ni = 0; ni < 4; ni++)
                ldsm2(bh[ni], uBh + ((wn * 32 + ni * 8 + (lane & 7)) * 40 + ((lane >> 3) & 1) * 8 + ks * 16) * 2);
            #pragma unroll
            for (int mi = 0; mi < 2; mi++)
                #pragma unroll
                for (int ni = 0; ni < 4; ni++)
                    mma_bf(c[mi][ni], ah[mi], bh[ni]);
        }
    }
    #undef V_LDG

    #pragma unroll
    for (int mi = 0; mi < 2; mi++)
        #pragma unroll
        for (int ni = 0; ni < 4; ni++) {
            int col = wn * 32 + ni * 8 + (lane & 3) * 2;
            #pragma unroll
            for (int half = 0; half < 2; half++) {
                int row = m0 + wm * 32 + mi * 16 + (lane >> 2) + half * 8;
                int b = row >> 11, s = row & 2047;
                size_t off = ((size_t)((b * NHEAD + h) * SEQ + s)) * DK + col;
                *(uint32_t*)(g_vp + off) =
                    pack_bf2f(c[mi][ni][half * 2], c[mi][ni][half * 2 + 1]);
            }
        }
}

// ============================================================================
// Scores (bf16x3): attn_raw[bh, q, k] with NEGV mask.  R4-proven version.
// ============================================================================
static constexpr int SC_T = 128 * 72;
static constexpr int SC_BYTES = 4 * SC_T * 2;            // 73728

__global__ __launch_bounds__(256)
void scores_mm(const int* __restrict__ mask, float* __restrict__ attn)
{
    extern __shared__ __align__(16) __nv_bfloat16 smem[];
    __nv_bfloat16* sQh = smem;
    __nv_bfloat16* sQl = smem + SC_T;
    __nv_bfloat16* sKh = smem + 2 * SC_T;
    __nv_bfloat16* sKl = smem + 3 * SC_T;

    const int tid = threadIdx.x;
    const int w = tid >> 5, lane = tid & 31;
    const int wm = w >> 2, wn = w & 3;       // 2 x 4
    const int k0 = blockIdx.x * 128;
    const int q0 = blockIdx.y * 128;
    const int bh = blockIdx.z;
    const int b  = bh >> 4;

    const size_t plane = (size_t)bh * SEQ * DK;
    const __nv_bfloat16* srcs[4] = {
        g_qhi + plane + (size_t)q0 * DK, g_qlo + plane + (size_t)q0 * DK,
        g_khi + plane + (size_t)k0 * DK, g_klo + plane + (size_t)k0 * DK };
    __nv_bfloat16* dsts[4] = { sQh, sQl, sKh, sKl };
    #pragma unroll
    for (int t = 0; t < 4; t++)
        for (int idx = tid; idx < 1024; idx += 256) {
            int r = idx >> 3, cc = (idx & 7) * 8;
            *(uint4*)(dsts[t] + r * 72 + cc) = *(const uint4*)(srcs[t] + (size_t)r * DK + cc);
        }
    __syncthreads();

    const uint32_t uQh = smem_u32(sQh), uQl = smem_u32(sQl);
    const uint32_t uKh = smem_u32(sKh), uKl = smem_u32(sKl);

    float c[4][4][4];
    #pragma unroll
    for (int mi = 0; mi < 4; mi++)
        #pragma unroll
        for (int ni = 0; ni < 4; ni++)
            #pragma unroll
            for (int r = 0; r < 4; r++) c[mi][ni][r] = 0.0f;

    #pragma unroll
    for (int pass = 0; pass < 3; pass++) {
        const uint32_t uA = (pass == 2) ? uQl : uQh;
        const uint32_t uB = (pass == 1) ? uKl : uKh;
        #pragma unroll
        for (int ks = 0; ks < 4; ks++) {
            uint32_t a[4][4], bf[4][2];
            #pragma unroll
            for (int mi = 0; mi < 4; mi++)
                ldsm4(a[mi], uA + ((wm * 64 + mi * 16 + (lane & 15)) * 72 + (lane >> 4) * 8 + ks * 16) * 2);
            #pragma unroll
            for (int ni = 0; ni < 4; ni++)
                ldsm2(bf[ni], uB + ((wn * 32 + ni * 8 + (lane & 7)) * 72 + ((lane >> 3) & 1) * 8 + ks * 16) * 2);
            #pragma unroll
            for (int mi = 0; mi < 4; mi++)
                #pragma unroll
                for (int ni = 0; ni < 4; ni++)
                    mma_bf(c[mi][ni], a[mi], bf[ni]);
        }
    }

    float* aplane = attn + (size_t)bh * SEQ * SEQ;
    const int* mplane = mask + (size_t)b * SEQ * SEQ;
    #pragma unroll
    for (int mi = 0; mi < 4; mi++)
        #pragma unroll
        for (int ni = 0; ni < 4; ni++) {
            int kcol = k0 + wn * 32 + ni * 8 + (lane & 3) * 2;
            #pragma unroll
            for (int half = 0; half < 2; half++) {
                int qrow = q0 + wm * 64 + mi * 16 + (lane >> 2) + half * 8;
                size_t off = (size_t)qrow * SEQ + kcol;
                int2 mv = *(const int2*)(mplane + off);
                float2 o;
                o.x = mv.x ? c[mi][ni][half * 2]     : NEGV;
                o.y = mv.y ? c[mi][ni][half * 2 + 1] : NEGV;
                *(float2*)(aplane + off) = o;
            }
        }
}

// ============================================================================
// Softmax in place (no max pass — validated numerics); emits bf16 P plane.
// ============================================================================
__global__ __launch_bounds__(256)
void softmax_kernel(float* __restrict__ attn)
{
    const size_t base = (size_t)blockIdx.x * SEQ;
    const int tid = threadIdx.x;
    const int wid = tid >> 5, lane = tid & 31;

    float4 v0 = *(float4*)(attn + base + (size_t)tid * 4);
    float4 v1 = *(float4*)(attn + base + (size_t)(tid + 256) * 4);

    float e[8];
    e[0] = __expf(fminf(v0.x, 80.0f)); e[1] = __expf(fminf(v0.y, 80.0f));
    e[2] = __expf(fminf(v0.z, 80.0f)); e[3] = __expf(fminf(v0.w, 80.0f));
    e[4] = __expf(fminf(v1.x, 80.0f)); e[5] = __expf(fminf(v1.y, 80.0f));
    e[6] = __expf(fminf(v1.z, 80.0f)); e[7] = __expf(fminf(v1.w, 80.0f));
    float s = e[0] + e[1] + e[2] + e[3] + e[4] + e[5] + e[6] + e[7];
    s = warp_sum(s);
    __shared__ float red[8];
    if (lane == 0) red[wid] = s;
    __syncthreads();
    float bs = (lane < 8) ? red[lane] : 0.0f;
    bs = warp_sum(bs);
    float inv = 1.0f / bs;

    float p[8];
    #pragma unroll
    for (int i = 0; i < 8; i++) p[i] = e[i] * inv;

    *(float4*)(attn + base + (size_t)tid * 4)         = make_float4(p[0], p[1], p[2], p[3]);
    *(float4*)(attn + base + (size_t)(tid + 256) * 4) = make_float4(p[4], p[5], p[6], p[7]);

    *(uint2*)(g_pb + base + (size_t)tid * 4) =
        make_uint2(pack_bf2f(p[0], p[1]), pack_bf2f(p[2], p[3]));
    *(uint2*)(g_pb + base + (size_t)(tid + 256) * 4) =
        make_uint2(pack_bf2f(p[4], p[5]), pack_bf2f(p[6], p[7]));
}

// ============================================================================
// PV (plain bf16) with register prefetch.  CTA 128q x 64d, k-chunk 64.
// ============================================================================
__global__ __launch_bounds__(256)
void pv_mm()
{
    __shared__ __align__(16) __nv_bfloat16 Ps[128 * 72];
    __shared__ __align__(16) __nv_bfloat16 Vs[64 * 72];

    const int tid = threadIdx.x;
    const int w = tid >> 5, lane = tid & 31;
    const int wm = w >> 1, wn = w & 1;       // 4 x 2
    const int q0 = blockIdx.x * 128;
    const int bh = blockIdx.y;
    const int b  = bh >> 4, h = bh & 15;

    const uint32_t uP = smem_u32(Ps), uV = smem_u32(Vs);
    const __nv_bfloat16* pb = g_pb + (size_t)bh * SEQ * SEQ + (size_t)q0 * SEQ;
    const __nv_bfloat16* vp = g_vp + (size_t)bh * SEQ * DK;

    const int pr = tid >> 3, pc = (tid & 7) * 8;   // P: 4 parts of 256 idx each
    const int vr = tid >> 3, vc = (tid & 7) * 8;   // V: 2 parts

    float c[2][4][4];
    #pragma unroll
    for (int mi = 0; mi < 2; mi++)
        #pragma unroll
        for (int ni = 0; ni < 4; ni++)
            #pragma unroll
            for (int r = 0; r < 4; r++) c[mi][ni][r] = 0.0f;

    uint4 pP[4], pV[2];
    #define PV_LDG(KC) do { const int _s0 = (KC) * 64;                                   \
        _Pragma("unroll")                                                                \
        for (int t = 0; t < 4; t++)                                                      \
            pP[t] = *(const uint4*)(pb + (size_t)(pr + t * 32) * SEQ + _s0 + pc);        \
        _Pragma("unroll")                                                                \
        for (int t = 0; t < 2; t++)                                                      \
            pV[t] = *(const uint4*)(vp + (size_t)(_s0 + vr + t * 32) * DK + vc);         \
    } while (0)

    PV_LDG(0);
    for (int kc = 0; kc < 32; kc++) {
        __syncthreads();
        #pragma unroll
        for (int t = 0; t < 4; t++)
            *(uint4*)(Ps + (pr + t * 32) * 72 + pc) = pP[t];
        #pragma unroll
        for (int t = 0; t < 2; t++)
            *(uint4*)(Vs + (vr + t * 32) * 72 + vc) = pV[t];
        __syncthreads();
        if (kc < 31) PV_LDG(kc + 1);

        #pragma unroll
        for (int ks = 0; ks < 4; ks++) {
            uint32_t a[2][4], bf[4][2];
            #pragma unroll
            for (int mi = 0; mi < 2; mi++)
                ldsm4(a[mi], uP + ((wm * 32 + mi * 16 + (lane & 15)) * 72 + (lane >> 4) * 8 + ks * 16) * 2);
            #pragma unroll
            for (int ni = 0; ni < 4; ni++)
                ldsm2t(bf[ni], uV + ((ks * 16 + (lane & 15)) * 72 + wn * 32 + ni * 8) * 2);
            #pragma unroll
            for (int mi = 0; mi < 2; mi++)
                #pragma unroll
                for (int ni = 0; ni < 4; ni++)
                    mma_bf(c[mi][ni], a[mi], bf[ni]);
        }
    }
    #undef PV_LDG

    #pragma unroll
    for (int mi = 0; mi < 2; mi++)
        #pragma unroll
        for (int ni = 0; ni < 4; ni++) {
            int d = wn * 32 + ni * 8 + (lane & 3) * 2;
            #pragma unroll
            for (int half = 0; half < 2; half++) {
                int s = q0 + wm * 32 + mi * 16 + (lane >> 2) + half * 8;
                size_t off = (size_t)(b * SEQ + s) * DMODEL + h * DK + d;
                uint32_t hi, lo;
                split2(c[mi][ni][half * 2], c[mi][ni][half * 2 + 1], hi, lo);
                *(uint32_t*)(g_ohi + off) = hi;
                *(uint32_t*)(g_olo + off) = lo;
            }
        }
}

// ============================================================================
// FC (bf16x3) + residual with register prefetch.
// ============================================================================
__global__ __launch_bounds__(256)
void gemm_fc(const float* __restrict__ qkv, float* __restrict__ out)
{
    const int n0 = blockIdx.x * 64;
    const int m0 = blockIdx.y * 128;

    __shared__ __align__(16) __nv_bfloat16 Ah[128 * 40], Al[128 * 40];
    __shared__ __align__(16) __nv_bfloat16 Bh[64 * 40],  Bl[64 * 40];

    const int tid = threadIdx.x;
    const int w = tid >> 5, lane = tid & 31;
    const int wm = w >> 1, wn = w & 1;
    const uint32_t uAh = smem_u32(Ah), uAl = smem_u32(Al);
    const uint32_t uBh = smem_u32(Bh), uBl = smem_u32(Bl);

    const int ar0 = tid >> 2, ac = (tid & 3) * 8;
    const int ar1 = (tid + 256) >> 2;

    float c[2][4][4];
    #pragma unroll
    for (int mi = 0; mi < 2; mi++)
        #pragma unroll
        for (int ni = 0; ni < 4; ni++)
            #pragma unroll
            for (int r = 0; r < 4; r++) c[mi][ni][r] = 0.0f;

    uint4 pAh0, pAh1, pAl0, pAl1, pBh, pBl;
    #define FC_LDG(KC) do { const int _k0 = (KC) * 32;                                   \
        pAh0 = *(const uint4*)(g_ohi + (size_t)(m0 + ar0) * DMODEL + _k0 + ac);          \
        pAh1 = *(const uint4*)(g_ohi + (size_t)(m0 + ar1) * DMODEL + _k0 + ac);          \
        pAl0 = *(const uint4*)(g_olo + (size_t)(m0 + ar0) * DMODEL + _k0 + ac);          \
        pAl1 = *(const uint4*)(g_olo + (size_t)(m0 + ar1) * DMODEL + _k0 + ac);          \
        pBh  = *(const uint4*)(g_wft_hi + (size_t)(n0 + ar0) * DMODEL + _k0 + ac);       \
        pBl  = *(const uint4*)(g_wft_lo + (size_t)(n0 + ar0) * DMODEL + _k0 + ac);       \
    } while (0)

    FC_LDG(0);
    for (int kc = 0; kc < 32; kc++) {
        __syncthreads();
        *(uint4*)(Ah + ar0 * 40 + ac) = pAh0;
        *(uint4*)(Ah + ar1 * 40 + ac) = pAh1;
        *(uint4*)(Al + ar0 * 40 + ac) = pAl0;
        *(uint4*)(Al + ar1 * 40 + ac) = pAl1;
        *(uint4*)(Bh + ar0 * 40 + ac) = pBh;
        *(uint4*)(Bl + ar0 * 40 + ac) = pBl;
        __syncthreads();
        if (kc < 31) FC_LDG(kc + 1);

        #pragma unroll
        for (int ks = 0; ks < 2; ks++) {
            uint32_t ah[2][4], al[2][4], bh[4][2], bl[4][2];
            #pragma unroll
            for (int mi = 0; mi < 2; mi++) {
                uint32_t off = ((wm * 32 + mi * 16 + (lane & 15)) * 40 + (lane >> 4) * 8 + ks * 16) * 2;
                ldsm4(ah[mi], uAh + off);
                ldsm4(al[mi], uAl + off);
            }
            #pragma unroll
            for (int ni = 0; ni < 4; ni++) {
                uint32_t off = ((wn * 32 + ni * 8 + (lane & 7)) * 40 + ((lane >> 3) & 1) * 8 + ks * 16) * 2;
                ldsm2(bh[ni], uBh + off);
                ldsm2(bl[ni], uBl + off);
            }
            #pragma unroll
            for (int mi = 0; mi < 2; mi++)
                #pragma unroll
                for (int ni = 0; ni < 4; ni++) {
                    mma_bf(c[mi][ni], ah[mi], bh[ni]);
                    mma_bf(c[mi][ni], ah[mi], bl[ni]);
                    mma_bf(c[mi][ni], al[mi], bh[ni]);
                }
        }
    }
    #undef FC_LDG

    #pragma unroll
    for (int mi = 0; mi < 2; mi++)
        #pragma unroll
        for (int ni = 0; ni < 4; ni++) {
            int col = n0 + wn * 32 + ni * 8 + (lane & 3) * 2;
            #pragma unroll
            for (int half = 0; half < 2; half++) {
                int row = m0 + wm * 32 + mi * 16 + (lane >> 2) + half * 8;
                size_t off = (size_t)row * DMODEL + col;
                float2 r = *(const float2*)(qkv + off);
                *(float2*)(out + off) =
                    make_float2(c[mi][ni][half * 2] + r.x, c[mi][ni][half * 2 + 1] + r.y);
            }
        }
}

// ============================================================================
// LayerNorm in place.
// ============================================================================
__global__ __launch_bounds__(256)
void ln_kernel(float* __restrict__ out,
               const float* __restrict__ gamma,
               const float* __restrict__ beta)
{
    const size_t base = (size_t)blockIdx.x * DMODEL;
    const int tid = threadIdx.x;
    const int wid = tid >> 5, lane = tid & 31;

    float4 v = *(float4*)(out + base + (size_t)tid * 4);
    float s  = v.x + v.y + v.z + v.w;
    float sq = v.x * v.x + v.y * v.y + v.z * v.z + v.w * v.w;
    s  = warp_sum(s);
    sq = warp_sum(sq);
    __shared__ float rs[8], rq[8];
    if (lane == 0) { rs[wid] = s; rq[wid] = sq; }
    __syncthreads();
    float ts = (lane < 8) ? rs[lane] : 0.0f; ts = warp_sum(ts);
    float tq = (lane < 8) ? rq[lane] : 0.0f; tq = warp_sum(tq);

    float mean = ts * (1.0f / DMODEL);
    float var  = tq * (1.0f / DMODEL) - mean * mean;
    float inv  = rsqrtf(var + 1e-6f);

    float4 g  = *(const float4*)(gamma + tid * 4);
    float4 bt = *(const float4*)(beta + tid * 4);
    float4 o;
    o.x = (v.x - mean) * inv * g.x + bt.x;
    o.y = (v.y - mean) * inv * g.y + bt.y;
    o.z = (v.z - mean) * inv * g.z + bt.z;
    o.w = (v.w - mean) * inv * g.w + bt.w;
    *(float4*)(out + base + (size_t)tid * 4) = o;
}

// ============================================================================
extern "C" void kernel_launch(void* const* d_in, const int* in_sizes, int n_in,
                              void* d_out, int out_size)
{
    (void)in_sizes; (void)n_in; (void)out_size;
    const float* qkv  = (const float*)d_in[0];
    const int*   mask = (const int*)  d_in[1];
    const float* w_qs = (const float*)d_in[2];
    const float* w_ks = (const float*)d_in[3];
    const float* w_vs = (const float*)d_in[4];
    const float* w_fc = (const float*)d_in[5];
    const float* ln_g = (const float*)d_in[6];
    const float* ln_b = (const float*)d_in[7];

    float* out_main = (float*)d_out;
    float* attn     = (float*)d_out + OUT_ELEMS;

    static bool attr_set = false;
    if (!attr_set) {
        cudaFuncSetAttribute(scores_mm, cudaFuncAttributeMaxDynamicSharedMemorySize, SC_BYTES);
        attr_set = true;
    }

    split_x   <<<BS * DMODEL / 4 / 256, 256>>>(qkv);
    wtrans    <<<dim3(32, 32, 4), 256>>>(w_qs, w_ks, w_vs, w_fc);
    gemm_qk   <<<dim3(NHEAD, BS / 128, 2), 256>>>();
    gemm_v    <<<dim3(NHEAD, BS / 128), 256>>>();
    scores_mm <<<dim3(SEQ / 128, SEQ / 128, BATCH * NHEAD), 256, SC_BYTES>>>(mask, attn);
    softmax_kernel<<<BATCH * NHEAD * SEQ, 256>>>(attn);
    pv_mm     <<<dim3(SEQ / 128, BATCH * NHEAD), 256>>>();
    gemm_fc   <<<dim3(DMODEL / 64, BS / 128), 256>>>(qkv, out_main);
    ln_kernel <<<BS, 256>>>(out_main, ln_g, ln_b);
}